// round 1
// baseline (speedup 1.0000x reference)
#include <cuda_runtime.h>
#include <cuda_bf16.h>
#include <math.h>

// ---------------- problem constants ----------------
#define BB    8
#define C_IN  2
#define IMG   256
#define PP    16
#define DD    1024
#define LL    8
#define NHH   16
#define DFF_  4096
#define HPP   16          // patches per side
#define NTOK  256         // HP*HP
#define STOK  257         // +cls
#define HD_   64          // head dim
#define KPAT  512         // C*P*P

// ---------------- scratch (static device memory; no allocs) ----------------
__device__ float g_x     [BB * STOK * DD];
__device__ float g_h     [BB * STOK * DD];
__device__ float g_q     [BB * STOK * DD];
__device__ float g_k     [BB * STOK * DD];
__device__ float g_v     [BB * STOK * DD];
__device__ float g_o     [BB * STOK * DD];
__device__ float g_res   [BB * NTOK * DD];
__device__ float g_patch [BB * NTOK * KPAT];
__device__ float g_mlp   [BB * STOK * DFF_];
__device__ float g_tok   [BB * NTOK * DD];
__device__ float g_pred  [BB * NTOK * (PP*PP*2)];

// ---------------- im2col for patch embed ----------------
__global__ void im2col_kernel(const float* __restrict__ imgs, float* __restrict__ patches)
{
    int idx = blockIdx.x * blockDim.x + threadIdx.x;
    const int total = BB * NTOK * KPAT;
    if (idx >= total) return;
    int k = idx % KPAT;
    int m = idx / KPAT;
    int n = m % NTOK;
    int b = m / NTOK;
    int h = n / HPP, w = n % HPP;
    int c = k / 256;
    int rem = k % 256;
    int p = rem / 16, q = rem % 16;
    patches[idx] = imgs[(((size_t)b * C_IN + c) * IMG + (h * PP + p)) * IMG + (w * PP + q)];
}

// ---------------- build x = [cls ; patch tokens] ----------------
__global__ void build_x_kernel(const float* __restrict__ res, const float* __restrict__ cls,
                               float* __restrict__ x)
{
    int idx = blockIdx.x * blockDim.x + threadIdx.x;
    const int total = BB * STOK * DD;
    if (idx >= total) return;
    int d = idx % DD;
    int r = idx / DD;
    int s = r % STOK;
    int b = r / STOK;
    x[idx] = (s == 0) ? cls[d] : res[((size_t)(b * NTOK + (s - 1))) * DD + d];
}

// ---------------- layernorm (two-pass, one block per row) ----------------
__global__ void ln_kernel(const float* __restrict__ X, const float* __restrict__ w,
                          const float* __restrict__ bvec, float* __restrict__ Y)
{
    __shared__ float red[256];
    int row = blockIdx.x;
    int tid = threadIdx.x;
    const float* xr = X + (size_t)row * DD;
    float v[4];
    float s = 0.f;
#pragma unroll
    for (int i = 0; i < 4; i++) { v[i] = xr[tid + i * 256]; s += v[i]; }
    red[tid] = s; __syncthreads();
    for (int off = 128; off; off >>= 1) { if (tid < off) red[tid] += red[tid + off]; __syncthreads(); }
    float mu = red[0] * (1.f / DD);
    __syncthreads();
    float s2 = 0.f;
#pragma unroll
    for (int i = 0; i < 4; i++) { float d = v[i] - mu; s2 += d * d; }
    red[tid] = s2; __syncthreads();
    for (int off = 128; off; off >>= 1) { if (tid < off) red[tid] += red[tid + off]; __syncthreads(); }
    float inv = rsqrtf(red[0] * (1.f / DD) + 1e-5f);
    float* yr = Y + (size_t)row * DD;
#pragma unroll
    for (int i = 0; i < 4; i++) {
        int c = tid + i * 256;
        yr[c] = (v[i] - mu) * inv * w[c] + bvec[c];
    }
}

// ---------------- generic SGEMM: C = A[M,K] @ W[K,N] + bias (+epilogue) ----------------
// EPI: 0 = bias only; 1 = bias + residual add; 2 = bias + exact GELU
template <int EPI>
__global__ __launch_bounds__(256)
void sgemm_kernel(const float* __restrict__ A, const float* __restrict__ W,
                  const float* __restrict__ bias, float* __restrict__ Cm,
                  const float* __restrict__ R, int M, int Nn, int K)
{
    __shared__ float As[8][128];
    __shared__ float Bs[8][128];
    int tid = threadIdx.x;
    int bm = blockIdx.y * 128;
    int bn = blockIdx.x * 128;
    int tx = tid & 15, ty = tid >> 4;

    float acc[8][8];
#pragma unroll
    for (int i = 0; i < 8; i++)
#pragma unroll
        for (int j = 0; j < 8; j++) acc[i][j] = 0.f;

    int arow = tid >> 1;
    int acol = (tid & 1) * 4;
    int brow = tid >> 5;
    int bcol = (tid & 31) * 4;
    bool arow_ok = (bm + arow) < M;
    const float* Aptr = A + (size_t)(bm + arow) * K + acol;

    for (int k0 = 0; k0 < K; k0 += 8) {
        float4 av = arow_ok ? *(const float4*)(Aptr + k0) : make_float4(0.f, 0.f, 0.f, 0.f);
        float4 bv = *(const float4*)(W + (size_t)(k0 + brow) * Nn + bn + bcol);
        As[acol + 0][arow] = av.x;
        As[acol + 1][arow] = av.y;
        As[acol + 2][arow] = av.z;
        As[acol + 3][arow] = av.w;
        *(float4*)&Bs[brow][bcol] = bv;
        __syncthreads();
#pragma unroll
        for (int kk = 0; kk < 8; kk++) {
            float ra[8], rb[8];
#pragma unroll
            for (int i = 0; i < 8; i++) ra[i] = As[kk][ty * 8 + i];
#pragma unroll
            for (int j = 0; j < 8; j++) rb[j] = Bs[kk][tx * 8 + j];
#pragma unroll
            for (int i = 0; i < 8; i++)
#pragma unroll
                for (int j = 0; j < 8; j++) acc[i][j] += ra[i] * rb[j];
        }
        __syncthreads();
    }

#pragma unroll
    for (int i = 0; i < 8; i++) {
        int row = bm + ty * 8 + i;
        if (row >= M) continue;
#pragma unroll
        for (int j = 0; j < 8; j++) {
            int col = bn + tx * 8 + j;
            float val = acc[i][j] + bias[col];
            if (EPI == 1) val += R[(size_t)row * Nn + col];
            if (EPI == 2) val = 0.5f * val * (1.f + erff(val * 0.70710678118654752f));
            Cm[(size_t)row * Nn + col] = val;
        }
    }
}

// ---------------- fused attention: logits + decay mask + softmax + P@V ----------------
// grid: (ceil(S/8), NH, B), block 256 (8 warps, one query row per warp)
__global__ __launch_bounds__(256)
void attn_kernel(const float* __restrict__ Q, const float* __restrict__ Kt,
                 const float* __restrict__ Vt, float* __restrict__ O)
{
    __shared__ float sQ[8][64];
    __shared__ float sKV[64][65];   // padded: conflict-free both access patterns
    __shared__ float sP[8][257];

    const int i0 = blockIdx.x * 8;
    const int h  = blockIdx.y;
    const int b  = blockIdx.z;
    const int warp = threadIdx.x >> 5;
    const int lane = threadIdx.x & 31;

    const float decay = logf(1.f - exp2f(-1.f - (float)h));

    // load q rows (pre-scaled by HD^-0.5)
    for (int idx = threadIdx.x; idx < 8 * 64; idx += 256) {
        int r = idx >> 6, d = idx & 63;
        int i = i0 + r;
        sQ[r][d] = (i < STOK) ? Q[((size_t)(b * STOK + i)) * DD + h * HD_ + d] * 0.125f : 0.f;
    }

    const int my_i = i0 + warp;
    int yq = 0, xq = 0;
    if (my_i > 0) { yq = (my_i - 1) >> 4; xq = (my_i - 1) & 15; }

    // pass 1: logits
    for (int j0 = 0; j0 < STOK; j0 += 64) {
        int rows = min(64, STOK - j0);
        __syncthreads();
        for (int idx = threadIdx.x; idx < rows * 64; idx += 256) {
            int r = idx >> 6, d = idx & 63;
            sKV[r][d] = Kt[((size_t)(b * STOK + j0 + r)) * DD + h * HD_ + d];
        }
        __syncthreads();
        if (my_i < STOK) {
            for (int jj = lane; jj < rows; jj += 32) {
                float s = 0.f;
#pragma unroll
                for (int d = 0; d < 64; d++) s += sQ[warp][d] * sKV[jj][d];
                int j = j0 + jj;
                if (my_i > 0 && j > 0) {
                    int yk = (j - 1) >> 4, xk = (j - 1) & 15;
                    s += decay * (float)(abs(yq - yk) + abs(xq - xk));
                }
                sP[warp][j] = s;
            }
        }
    }

    // softmax (per-warp row, no cross-warp sharing of sP)
    if (my_i < STOK) {
        float m = -1e30f;
        for (int j = lane; j < STOK; j += 32) m = fmaxf(m, sP[warp][j]);
#pragma unroll
        for (int o = 16; o; o >>= 1) m = fmaxf(m, __shfl_xor_sync(0xffffffffu, m, o));
        float sum = 0.f;
        for (int j = lane; j < STOK; j += 32) {
            float e = __expf(sP[warp][j] - m);
            sP[warp][j] = e;
            sum += e;
        }
#pragma unroll
        for (int o = 16; o; o >>= 1) sum += __shfl_xor_sync(0xffffffffu, sum, o);
        float inv = 1.f / sum;
        for (int j = lane; j < STOK; j += 32) sP[warp][j] *= inv;
    }

    // pass 2: O = P @ V
    float acc0 = 0.f, acc1 = 0.f;
    for (int j0 = 0; j0 < STOK; j0 += 64) {
        int rows = min(64, STOK - j0);
        __syncthreads();
        for (int idx = threadIdx.x; idx < rows * 64; idx += 256) {
            int r = idx >> 6, d = idx & 63;
            sKV[r][d] = Vt[((size_t)(b * STOK + j0 + r)) * DD + h * HD_ + d];
        }
        __syncthreads();
        if (my_i < STOK) {
            for (int jj = 0; jj < rows; jj++) {
                float p = sP[warp][j0 + jj];
                acc0 += p * sKV[jj][lane];
                acc1 += p * sKV[jj][lane + 32];
            }
        }
    }
    if (my_i < STOK) {
        size_t base = ((size_t)(b * STOK + my_i)) * DD + h * HD_;
        O[base + lane]      = acc0;
        O[base + lane + 32] = acc1;
    }
}

// ---------------- PGSA gating + residual ----------------
// one block per (b, d); 256 threads = 256 patch tokens
__global__ void pgsa_kernel(const float* __restrict__ XF, const float* __restrict__ RES,
                            float* __restrict__ TOK)
{
    __shared__ float red[256];
    int d = blockIdx.x % DD;
    int b = blockIdx.x / DD;
    int n = threadIdx.x;

    float t = XF[((size_t)(b * STOK) + 1 + n) * DD + d];

    red[n] = t; __syncthreads();
    for (int off = 128; off; off >>= 1) { if (n < off) red[n] += red[n + off]; __syncthreads(); }
    float mu = red[0] * (1.f / NTOK);
    __syncthreads();

    float dm = t - mu;
    float xm2 = dm * dm;
    red[n] = xm2; __syncthreads();
    for (int off = 128; off; off >>= 1) { if (n < off) red[n] += red[n + off]; __syncthreads(); }
    float s2 = red[0];

    float y = xm2 / (4.f * (s2 * (1.f / 255.f) + 1e-4f)) + 0.5f;
    float sig = 1.f / (1.f + __expf(-y));
    TOK[((size_t)(b * NTOK + n)) * DD + d] = t * sig + RES[((size_t)(b * NTOK + n)) * DD + d];
}

// ---------------- unpatchify ----------------
__global__ void unpatch_kernel(const float* __restrict__ pred, float* __restrict__ out)
{
    int idx = blockIdx.x * blockDim.x + threadIdx.x;
    const int total = BB * 2 * IMG * IMG;
    if (idx >= total) return;
    int r  = idx % (2 * IMG * IMG);
    int b  = idx / (2 * IMG * IMG);
    int c  = r / (IMG * IMG);
    int r2 = r % (IMG * IMG);
    int y  = r2 / IMG, x = r2 % IMG;
    int h = y >> 4, p = y & 15, w = x >> 4, q = x & 15;
    out[idx] = pred[((size_t)(b * NTOK + h * HPP + w)) * (PP * PP * 2) + ((p * 16 + q) * 2 + c)];
}

// ---------------- host orchestration ----------------
static inline void launch_gemm(int epi, const float* A, const float* W, const float* bias,
                               float* Cm, const float* R, int M, int Nn, int K)
{
    dim3 grid(Nn / 128, (M + 127) / 128);
    if (epi == 0)      sgemm_kernel<0><<<grid, 256>>>(A, W, bias, Cm, R, M, Nn, K);
    else if (epi == 1) sgemm_kernel<1><<<grid, 256>>>(A, W, bias, Cm, R, M, Nn, K);
    else               sgemm_kernel<2><<<grid, 256>>>(A, W, bias, Cm, R, M, Nn, K);
}

extern "C" void kernel_launch(void* const* d_in, const int* in_sizes, int n_in,
                              void* d_out, int out_size)
{
    const float* imgs     = (const float*)d_in[0];
    const float* patch_w  = (const float*)d_in[1];
    const float* patch_b  = (const float*)d_in[2];
    const float* cls_tok  = (const float*)d_in[3];
    const float* ln1_w    = (const float*)d_in[4];
    const float* ln1_b    = (const float*)d_in[5];
    const float* wq       = (const float*)d_in[6];
    const float* wk       = (const float*)d_in[7];
    const float* wv       = (const float*)d_in[8];
    const float* bq       = (const float*)d_in[9];
    const float* bk       = (const float*)d_in[10];
    const float* bv       = (const float*)d_in[11];
    const float* wo       = (const float*)d_in[12];
    const float* bo       = (const float*)d_in[13];
    const float* ln2_w    = (const float*)d_in[14];
    const float* ln2_b    = (const float*)d_in[15];
    const float* w1       = (const float*)d_in[16];
    const float* b1       = (const float*)d_in[17];
    const float* w2       = (const float*)d_in[18];
    const float* b2       = (const float*)d_in[19];
    const float* normf_w  = (const float*)d_in[20];
    const float* normf_b  = (const float*)d_in[21];
    const float* enpred_w = (const float*)d_in[22];
    const float* enpred_b = (const float*)d_in[23];

    float *x, *h, *q, *k, *v, *o, *res, *patches, *mlp, *tok, *pred;
    cudaGetSymbolAddress((void**)&x,       g_x);
    cudaGetSymbolAddress((void**)&h,       g_h);
    cudaGetSymbolAddress((void**)&q,       g_q);
    cudaGetSymbolAddress((void**)&k,       g_k);
    cudaGetSymbolAddress((void**)&v,       g_v);
    cudaGetSymbolAddress((void**)&o,       g_o);
    cudaGetSymbolAddress((void**)&res,     g_res);
    cudaGetSymbolAddress((void**)&patches, g_patch);
    cudaGetSymbolAddress((void**)&mlp,     g_mlp);
    cudaGetSymbolAddress((void**)&tok,     g_tok);
    cudaGetSymbolAddress((void**)&pred,    g_pred);

    const int Mtok = BB * STOK;   // 2056
    const int Mpat = BB * NTOK;   // 2048

    // patch embed
    im2col_kernel<<<(Mpat * KPAT + 255) / 256, 256>>>(imgs, patches);
    launch_gemm(0, patches, patch_w, patch_b, res, nullptr, Mpat, DD, KPAT);
    build_x_kernel<<<(BB * STOK * DD + 255) / 256, 256>>>(res, cls_tok, x);

    for (int i = 0; i < LL; i++) {
        const size_t wOff  = (size_t)i * DD * DD;
        const size_t bOff  = (size_t)i * DD;
        // attention block
        ln_kernel<<<Mtok, 256>>>(x, ln1_w + bOff, ln1_b + bOff, h);
        launch_gemm(0, h, wq + wOff, bq + bOff, q, nullptr, Mtok, DD, DD);
        launch_gemm(0, h, wk + wOff, bk + bOff, k, nullptr, Mtok, DD, DD);
        launch_gemm(0, h, wv + wOff, bv + bOff, v, nullptr, Mtok, DD, DD);
        attn_kernel<<<dim3((STOK + 7) / 8, NHH, BB), 256>>>(q, k, v, o);
        launch_gemm(1, o, wo + wOff, bo + bOff, x, x, Mtok, DD, DD);
        // MLP block
        ln_kernel<<<Mtok, 256>>>(x, ln2_w + bOff, ln2_b + bOff, h);
        launch_gemm(2, h, w1 + (size_t)i * DD * DFF_, b1 + (size_t)i * DFF_, mlp, nullptr, Mtok, DFF_, DD);
        launch_gemm(1, mlp, w2 + (size_t)i * DFF_ * DD, b2 + bOff, x, x, Mtok, DD, DFF_);
    }

    // final LN + PGSA + prediction head + unpatchify
    ln_kernel<<<Mtok, 256>>>(x, normf_w, normf_b, h);
    pgsa_kernel<<<BB * DD, 256>>>(h, res, tok);
    launch_gemm(0, tok, enpred_w, enpred_b, pred, nullptr, Mpat, PP * PP * 2, DD);
    unpatch_kernel<<<(out_size + 255) / 256, 256>>>(pred, (float*)d_out);
}

// round 4
// speedup vs baseline: 1.5452x; 1.5452x over previous
#include <cuda_runtime.h>
#include <cuda_bf16.h>
#include <math.h>

// ---------------- problem constants ----------------
#define BB    8
#define C_IN  2
#define IMG   256
#define PP    16
#define DD    1024
#define LL    8
#define NHH   16
#define DFF_  4096
#define HPP   16          // patches per side
#define NTOK  256         // HP*HP
#define STOK  257         // +cls
#define HD_   64          // head dim
#define KPAT  512         // C*P*P

// ---------------- scratch (static device memory; no allocs) ----------------
__device__ float g_x     [BB * STOK * DD];
__device__ float g_h     [BB * STOK * DD];
__device__ float g_q     [BB * STOK * DD];
__device__ float g_k     [BB * STOK * DD];
__device__ float g_v     [BB * STOK * DD];
__device__ float g_o     [BB * STOK * DD];
__device__ float g_res   [BB * NTOK * DD];
__device__ float g_patch [BB * NTOK * KPAT];
__device__ float g_mlp   [BB * STOK * DFF_];
__device__ float g_tok   [BB * NTOK * DD];
__device__ float g_pred  [BB * NTOK * (PP*PP*2)];

// ---------------- im2col for patch embed ----------------
__global__ void im2col_kernel(const float* __restrict__ imgs, float* __restrict__ patches)
{
    int idx = blockIdx.x * blockDim.x + threadIdx.x;
    const int total = BB * NTOK * KPAT;
    if (idx >= total) return;
    int k = idx % KPAT;
    int m = idx / KPAT;
    int n = m % NTOK;
    int b = m / NTOK;
    int h = n / HPP, w = n % HPP;
    int c = k / 256;
    int rem = k % 256;
    int p = rem / 16, q = rem % 16;
    patches[idx] = imgs[(((size_t)b * C_IN + c) * IMG + (h * PP + p)) * IMG + (w * PP + q)];
}

// ---------------- build x = [cls ; patch tokens] ----------------
__global__ void build_x_kernel(const float* __restrict__ res, const float* __restrict__ cls,
                               float* __restrict__ x)
{
    int idx = blockIdx.x * blockDim.x + threadIdx.x;
    const int total = BB * STOK * DD;
    if (idx >= total) return;
    int d = idx % DD;
    int r = idx / DD;
    int s = r % STOK;
    int b = r / STOK;
    x[idx] = (s == 0) ? cls[d] : res[((size_t)(b * NTOK + (s - 1))) * DD + d];
}

// ---------------- layernorm (two-pass, one block per row) ----------------
__global__ void ln_kernel(const float* __restrict__ X, const float* __restrict__ w,
                          const float* __restrict__ bvec, float* __restrict__ Y)
{
    __shared__ float red[256];
    int row = blockIdx.x;
    int tid = threadIdx.x;
    const float* xr = X + (size_t)row * DD;
    float v[4];
    float s = 0.f;
#pragma unroll
    for (int i = 0; i < 4; i++) { v[i] = xr[tid + i * 256]; s += v[i]; }
    red[tid] = s; __syncthreads();
    for (int off = 128; off; off >>= 1) { if (tid < off) red[tid] += red[tid + off]; __syncthreads(); }
    float mu = red[0] * (1.f / DD);
    __syncthreads();
    float s2 = 0.f;
#pragma unroll
    for (int i = 0; i < 4; i++) { float d = v[i] - mu; s2 += d * d; }
    red[tid] = s2; __syncthreads();
    for (int off = 128; off; off >>= 1) { if (tid < off) red[tid] += red[tid + off]; __syncthreads(); }
    float inv = rsqrtf(red[0] * (1.f / DD) + 1e-5f);
    float* yr = Y + (size_t)row * DD;
#pragma unroll
    for (int i = 0; i < 4; i++) {
        int c = tid + i * 256;
        yr[c] = (v[i] - mu) * inv * w[c] + bvec[c];
    }
}

// ---------------- tensor-core GEMM (bf16 split-precision, fp32-accurate) ----------------
// C = A[M,K] @ W[K,N] + bias (+epilogue). All K multiples of 32, N multiples of 128.
// EPI: 0 = bias only; 1 = bias + residual add; 2 = bias + exact GELU

__device__ __forceinline__ void mma_bf16(float* c, const unsigned* a, const unsigned* b)
{
    asm volatile(
        "mma.sync.aligned.m16n8k16.row.col.f32.bf16.bf16.f32 "
        "{%0,%1,%2,%3}, {%4,%5,%6,%7}, {%8,%9}, {%0,%1,%2,%3};\n"
        : "+f"(c[0]), "+f"(c[1]), "+f"(c[2]), "+f"(c[3])
        : "r"(a[0]), "r"(a[1]), "r"(a[2]), "r"(a[3]), "r"(b[0]), "r"(b[1]));
}

template <int EPI>
__global__ __launch_bounds__(256)
void tgemm_kernel(const float* __restrict__ A, const float* __restrict__ W,
                  const float* __restrict__ bias, float* __restrict__ Cm,
                  const float* __restrict__ R, int M, int Nn, int K)
{
    // padded rows (40) -> conflict-free 32-bit fragment loads
    __shared__ __nv_bfloat16 AsH[128][40];
    __shared__ __nv_bfloat16 AsL[128][40];
    __shared__ __nv_bfloat16 BsH[128][40];   // [n][k] (transposed)
    __shared__ __nv_bfloat16 BsL[128][40];

    const int tid  = threadIdx.x;
    const int bm   = blockIdx.y * 128;
    const int bn   = blockIdx.x * 128;
    const int warp = tid >> 5, lane = tid & 31;
    const int wm   = warp >> 2, wn = warp & 3;   // warp tile: 64 x 32
    const int g    = lane >> 2, t = lane & 3;

    float acc[4][4][4];
#pragma unroll
    for (int mt = 0; mt < 4; mt++)
#pragma unroll
        for (int nt = 0; nt < 4; nt++)
#pragma unroll
            for (int i = 0; i < 4; i++) acc[mt][nt][i] = 0.f;

    // global tile loaders
    const int arow = tid >> 1, acol = (tid & 1) * 16;      // A: 128 x 32 fp32
    const int bkr  = tid >> 3, bcol = (tid & 7) * 16;      // B: 32 x 128 fp32
    const bool aok = (bm + arow) < M;
    const float* Ag = A + (size_t)(bm + arow) * K + acol;
    const float* Bg = W + (size_t)bkr * Nn + bn + bcol;

    float4 pa[4], pb[4];
#pragma unroll
    for (int i = 0; i < 4; i++) {
        pa[i] = aok ? *(const float4*)(Ag + 4 * i) : make_float4(0.f, 0.f, 0.f, 0.f);
        pb[i] = *(const float4*)(Bg + 4 * i);
    }

    for (int k0 = 0; k0 < K; k0 += 32) {
        // stage current tile into smem as bf16 hi/lo
#pragma unroll
        for (int i = 0; i < 4; i++) {
            float fa[4] = { pa[i].x, pa[i].y, pa[i].z, pa[i].w };
#pragma unroll
            for (int j = 0; j < 4; j += 2) {
                __nv_bfloat16 h0 = __float2bfloat16(fa[j]);
                __nv_bfloat16 h1 = __float2bfloat16(fa[j + 1]);
                __nv_bfloat16 l0 = __float2bfloat16(fa[j] - __bfloat162float(h0));
                __nv_bfloat16 l1 = __float2bfloat16(fa[j + 1] - __bfloat162float(h1));
                __nv_bfloat162 ph; ph.x = h0; ph.y = h1;
                __nv_bfloat162 pl; pl.x = l0; pl.y = l1;
                *(__nv_bfloat162*)&AsH[arow][acol + 4 * i + j] = ph;
                *(__nv_bfloat162*)&AsL[arow][acol + 4 * i + j] = pl;
            }
            float fb[4] = { pb[i].x, pb[i].y, pb[i].z, pb[i].w };
#pragma unroll
            for (int j = 0; j < 4; j++) {
                __nv_bfloat16 h = __float2bfloat16(fb[j]);
                __nv_bfloat16 l = __float2bfloat16(fb[j] - __bfloat162float(h));
                BsH[bcol + 4 * i + j][bkr] = h;
                BsL[bcol + 4 * i + j][bkr] = l;
            }
        }
        __syncthreads();

        // prefetch next tile
        if (k0 + 32 < K) {
#pragma unroll
            for (int i = 0; i < 4; i++) {
                pa[i] = aok ? *(const float4*)(Ag + k0 + 32 + 4 * i) : make_float4(0.f, 0.f, 0.f, 0.f);
                pb[i] = *(const float4*)(Bg + (size_t)(k0 + 32) * Nn + 4 * i);
            }
        }

        // compute: 2 k-steps of 16
#pragma unroll
        for (int ks = 0; ks < 32; ks += 16) {
            unsigned aH[4][4], aL[4][4];
#pragma unroll
            for (int mt = 0; mt < 4; mt++) {
                int r0 = wm * 64 + mt * 16 + g;
                aH[mt][0] = *(const unsigned*)&AsH[r0][ks + 2 * t];
                aH[mt][1] = *(const unsigned*)&AsH[r0 + 8][ks + 2 * t];
                aH[mt][2] = *(const unsigned*)&AsH[r0][ks + 2 * t + 8];
                aH[mt][3] = *(const unsigned*)&AsH[r0 + 8][ks + 2 * t + 8];
                aL[mt][0] = *(const unsigned*)&AsL[r0][ks + 2 * t];
                aL[mt][1] = *(const unsigned*)&AsL[r0 + 8][ks + 2 * t];
                aL[mt][2] = *(const unsigned*)&AsL[r0][ks + 2 * t + 8];
                aL[mt][3] = *(const unsigned*)&AsL[r0 + 8][ks + 2 * t + 8];
            }
#pragma unroll
            for (int nt = 0; nt < 4; nt++) {
                int c0 = wn * 32 + nt * 8 + g;
                unsigned bH[2], bL[2];
                bH[0] = *(const unsigned*)&BsH[c0][ks + 2 * t];
                bH[1] = *(const unsigned*)&BsH[c0][ks + 2 * t + 8];
                bL[0] = *(const unsigned*)&BsL[c0][ks + 2 * t];
                bL[1] = *(const unsigned*)&BsL[c0][ks + 2 * t + 8];
#pragma unroll
                for (int mt = 0; mt < 4; mt++) {
                    mma_bf16(acc[mt][nt], aH[mt], bH);
                    mma_bf16(acc[mt][nt], aH[mt], bL);
                    mma_bf16(acc[mt][nt], aL[mt], bH);
                }
            }
        }
        __syncthreads();
    }

    // epilogue
#pragma unroll
    for (int mt = 0; mt < 4; mt++) {
        int r0 = bm + wm * 64 + mt * 16 + g;
#pragma unroll
        for (int nt = 0; nt < 4; nt++) {
            int col = bn + wn * 32 + nt * 8 + 2 * t;
            float b0 = bias[col], b1 = bias[col + 1];
#pragma unroll
            for (int half = 0; half < 2; half++) {
                int row = r0 + half * 8;
                if (row >= M) continue;
                float v0 = acc[mt][nt][half * 2 + 0] + b0;
                float v1 = acc[mt][nt][half * 2 + 1] + b1;
                if (EPI == 1) {
                    const float2 r2 = *(const float2*)&R[(size_t)row * Nn + col];
                    v0 += r2.x; v1 += r2.y;
                }
                if (EPI == 2) {
                    v0 = 0.5f * v0 * (1.f + erff(v0 * 0.70710678118654752f));
                    v1 = 0.5f * v1 * (1.f + erff(v1 * 0.70710678118654752f));
                }
                float2 outv; outv.x = v0; outv.y = v1;
                *(float2*)&Cm[(size_t)row * Nn + col] = outv;
            }
        }
    }
}

// ---------------- fused attention: logits + decay mask + softmax + P@V ----------------
__global__ __launch_bounds__(256)
void attn_kernel(const float* __restrict__ Q, const float* __restrict__ Kt,
                 const float* __restrict__ Vt, float* __restrict__ O)
{
    __shared__ float sQ[8][64];
    __shared__ float sKV[64][65];
    __shared__ float sP[8][257];

    const int i0 = blockIdx.x * 8;
    const int h  = blockIdx.y;
    const int b  = blockIdx.z;
    const int warp = threadIdx.x >> 5;
    const int lane = threadIdx.x & 31;

    const float decay = logf(1.f - exp2f(-1.f - (float)h));

    for (int idx = threadIdx.x; idx < 8 * 64; idx += 256) {
        int r = idx >> 6, d = idx & 63;
        int i = i0 + r;
        sQ[r][d] = (i < STOK) ? Q[((size_t)(b * STOK + i)) * DD + h * HD_ + d] * 0.125f : 0.f;
    }

    const int my_i = i0 + warp;
    int yq = 0, xq = 0;
    if (my_i > 0) { yq = (my_i - 1) >> 4; xq = (my_i - 1) & 15; }

    for (int j0 = 0; j0 < STOK; j0 += 64) {
        int rows = min(64, STOK - j0);
        __syncthreads();
        for (int idx = threadIdx.x; idx < rows * 64; idx += 256) {
            int r = idx >> 6, d = idx & 63;
            sKV[r][d] = Kt[((size_t)(b * STOK + j0 + r)) * DD + h * HD_ + d];
        }
        __syncthreads();
        if (my_i < STOK) {
            for (int jj = lane; jj < rows; jj += 32) {
                float s = 0.f;
#pragma unroll
                for (int d = 0; d < 64; d++) s += sQ[warp][d] * sKV[jj][d];
                int j = j0 + jj;
                if (my_i > 0 && j > 0) {
                    int yk = (j - 1) >> 4, xk = (j - 1) & 15;
                    s += decay * (float)(abs(yq - yk) + abs(xq - xk));
                }
                sP[warp][j] = s;
            }
        }
    }

    if (my_i < STOK) {
        float m = -1e30f;
        for (int j = lane; j < STOK; j += 32) m = fmaxf(m, sP[warp][j]);
#pragma unroll
        for (int o = 16; o; o >>= 1) m = fmaxf(m, __shfl_xor_sync(0xffffffffu, m, o));
        float sum = 0.f;
        for (int j = lane; j < STOK; j += 32) {
            float e = __expf(sP[warp][j] - m);
            sP[warp][j] = e;
            sum += e;
        }
#pragma unroll
        for (int o = 16; o; o >>= 1) sum += __shfl_xor_sync(0xffffffffu, sum, o);
        float inv = 1.f / sum;
        for (int j = lane; j < STOK; j += 32) sP[warp][j] *= inv;
    }

    float acc0 = 0.f, acc1 = 0.f;
    for (int j0 = 0; j0 < STOK; j0 += 64) {
        int rows = min(64, STOK - j0);
        __syncthreads();
        for (int idx = threadIdx.x; idx < rows * 64; idx += 256) {
            int r = idx >> 6, d = idx & 63;
            sKV[r][d] = Vt[((size_t)(b * STOK + j0 + r)) * DD + h * HD_ + d];
        }
        __syncthreads();
        if (my_i < STOK) {
            for (int jj = 0; jj < rows; jj++) {
                float p = sP[warp][j0 + jj];
                acc0 += p * sKV[jj][lane];
                acc1 += p * sKV[jj][lane + 32];
            }
        }
    }
    if (my_i < STOK) {
        size_t base = ((size_t)(b * STOK + my_i)) * DD + h * HD_;
        O[base + lane]      = acc0;
        O[base + lane + 32] = acc1;
    }
}

// ---------------- PGSA gating + residual ----------------
__global__ void pgsa_kernel(const float* __restrict__ XF, const float* __restrict__ RES,
                            float* __restrict__ TOK)
{
    __shared__ float red[256];
    int d = blockIdx.x % DD;
    int b = blockIdx.x / DD;
    int n = threadIdx.x;

    float t = XF[((size_t)(b * STOK) + 1 + n) * DD + d];

    red[n] = t; __syncthreads();
    for (int off = 128; off; off >>= 1) { if (n < off) red[n] += red[n + off]; __syncthreads(); }
    float mu = red[0] * (1.f / NTOK);
    __syncthreads();

    float dm = t - mu;
    float xm2 = dm * dm;
    red[n] = xm2; __syncthreads();
    for (int off = 128; off; off >>= 1) { if (n < off) red[n] += red[n + off]; __syncthreads(); }
    float s2 = red[0];

    float y = xm2 / (4.f * (s2 * (1.f / 255.f) + 1e-4f)) + 0.5f;
    float sig = 1.f / (1.f + __expf(-y));
    TOK[((size_t)(b * NTOK + n)) * DD + d] = t * sig + RES[((size_t)(b * NTOK + n)) * DD + d];
}

// ---------------- unpatchify ----------------
__global__ void unpatch_kernel(const float* __restrict__ pred, float* __restrict__ out)
{
    int idx = blockIdx.x * blockDim.x + threadIdx.x;
    const int total = BB * 2 * IMG * IMG;
    if (idx >= total) return;
    int r  = idx % (2 * IMG * IMG);
    int b  = idx / (2 * IMG * IMG);
    int c  = r / (IMG * IMG);
    int r2 = r % (IMG * IMG);
    int y  = r2 / IMG, x = r2 % IMG;
    int h = y >> 4, p = y & 15, w = x >> 4, q = x & 15;
    out[idx] = pred[((size_t)(b * NTOK + h * HPP + w)) * (PP * PP * 2) + ((p * 16 + q) * 2 + c)];
}

// ---------------- host orchestration ----------------
static inline void launch_gemm(int epi, const float* A, const float* W, const float* bias,
                               float* Cm, const float* R, int M, int Nn, int K)
{
    dim3 grid(Nn / 128, (M + 127) / 128);
    if (epi == 0)      tgemm_kernel<0><<<grid, 256>>>(A, W, bias, Cm, R, M, Nn, K);
    else if (epi == 1) tgemm_kernel<1><<<grid, 256>>>(A, W, bias, Cm, R, M, Nn, K);
    else               tgemm_kernel<2><<<grid, 256>>>(A, W, bias, Cm, R, M, Nn, K);
}

extern "C" void kernel_launch(void* const* d_in, const int* in_sizes, int n_in,
                              void* d_out, int out_size)
{
    const float* imgs     = (const float*)d_in[0];
    const float* patch_w  = (const float*)d_in[1];
    const float* patch_b  = (const float*)d_in[2];
    const float* cls_tok  = (const float*)d_in[3];
    const float* ln1_w    = (const float*)d_in[4];
    const float* ln1_b    = (const float*)d_in[5];
    const float* wq       = (const float*)d_in[6];
    const float* wk       = (const float*)d_in[7];
    const float* wv       = (const float*)d_in[8];
    const float* bq       = (const float*)d_in[9];
    const float* bk       = (const float*)d_in[10];
    const float* bv       = (const float*)d_in[11];
    const float* wo       = (const float*)d_in[12];
    const float* bo       = (const float*)d_in[13];
    const float* ln2_w    = (const float*)d_in[14];
    const float* ln2_b    = (const float*)d_in[15];
    const float* w1       = (const float*)d_in[16];
    const float* b1       = (const float*)d_in[17];
    const float* w2       = (const float*)d_in[18];
    const float* b2       = (const float*)d_in[19];
    const float* normf_w  = (const float*)d_in[20];
    const float* normf_b  = (const float*)d_in[21];
    const float* enpred_w = (const float*)d_in[22];
    const float* enpred_b = (const float*)d_in[23];

    float *x, *h, *q, *k, *v, *o, *res, *patches, *mlp, *tok, *pred;
    cudaGetSymbolAddress((void**)&x,       g_x);
    cudaGetSymbolAddress((void**)&h,       g_h);
    cudaGetSymbolAddress((void**)&q,       g_q);
    cudaGetSymbolAddress((void**)&k,       g_k);
    cudaGetSymbolAddress((void**)&v,       g_v);
    cudaGetSymbolAddress((void**)&o,       g_o);
    cudaGetSymbolAddress((void**)&res,     g_res);
    cudaGetSymbolAddress((void**)&patches, g_patch);
    cudaGetSymbolAddress((void**)&mlp,     g_mlp);
    cudaGetSymbolAddress((void**)&tok,     g_tok);
    cudaGetSymbolAddress((void**)&pred,    g_pred);

    const int Mtok = BB * STOK;   // 2056
    const int Mpat = BB * NTOK;   // 2048

    // patch embed
    im2col_kernel<<<(Mpat * KPAT + 255) / 256, 256>>>(imgs, patches);
    launch_gemm(0, patches, patch_w, patch_b, res, nullptr, Mpat, DD, KPAT);
    build_x_kernel<<<(BB * STOK * DD + 255) / 256, 256>>>(res, cls_tok, x);

    for (int i = 0; i < LL; i++) {
        const size_t wOff  = (size_t)i * DD * DD;
        const size_t bOff  = (size_t)i * DD;
        // attention block
        ln_kernel<<<Mtok, 256>>>(x, ln1_w + bOff, ln1_b + bOff, h);
        launch_gemm(0, h, wq + wOff, bq + bOff, q, nullptr, Mtok, DD, DD);
        launch_gemm(0, h, wk + wOff, bk + bOff, k, nullptr, Mtok, DD, DD);
        launch_gemm(0, h, wv + wOff, bv + bOff, v, nullptr, Mtok, DD, DD);
        attn_kernel<<<dim3((STOK + 7) / 8, NHH, BB), 256>>>(q, k, v, o);
        launch_gemm(1, o, wo + wOff, bo + bOff, x, x, Mtok, DD, DD);
        // MLP block
        ln_kernel<<<Mtok, 256>>>(x, ln2_w + bOff, ln2_b + bOff, h);
        launch_gemm(2, h, w1 + (size_t)i * DD * DFF_, b1 + (size_t)i * DFF_, mlp, nullptr, Mtok, DFF_, DD);
        launch_gemm(1, mlp, w2 + (size_t)i * DFF_ * DD, b2 + bOff, x, x, Mtok, DD, DFF_);
    }

    // final LN + PGSA + prediction head + unpatchify
    ln_kernel<<<Mtok, 256>>>(x, normf_w, normf_b, h);
    pgsa_kernel<<<BB * DD, 256>>>(h, res, tok);
    launch_gemm(0, tok, enpred_w, enpred_b, pred, nullptr, Mpat, PP * PP * 2, DD);
    unpatch_kernel<<<(out_size + 255) / 256, 256>>>(pred, (float*)d_out);
}

// round 5
// speedup vs baseline: 2.3732x; 1.5359x over previous
#include <cuda_runtime.h>
#include <cuda_bf16.h>
#include <math.h>
#include <stdint.h>

// ---------------- problem constants ----------------
#define BB    8
#define C_IN  2
#define IMG   256
#define PP    16
#define DD    1024
#define LL    8
#define NHH   16
#define DFF_  4096
#define HPP   16
#define NTOK  256
#define STOK  257
#define HD_   64
#define KPAT  512
#define QKVN  3072

// ---------------- static scratch (no allocations) ----------------
// fp32
__device__ float g_x    [BB * STOK * DD];
__device__ float g_h    [BB * STOK * DD];
__device__ float g_qkv  [BB * STOK * QKVN];
__device__ float g_res  [BB * NTOK * DD];
__device__ float g_pred [BB * NTOK * (PP*PP*2)];
__device__ float g_bqkv [LL * QKVN];
// split activations (bf16 hi/lo)
__device__ __nv_bfloat16 g_hH[BB*STOK*DD],   g_hL[BB*STOK*DD];
__device__ __nv_bfloat16 g_oH[BB*STOK*DD],   g_oL[BB*STOK*DD];
__device__ __nv_bfloat16 g_mlpH[BB*STOK*DFF_], g_mlpL[BB*STOK*DFF_];
__device__ __nv_bfloat16 g_pH[BB*NTOK*KPAT], g_pL[BB*NTOK*KPAT];
__device__ __nv_bfloat16 g_tokH[BB*NTOK*DD], g_tokL[BB*NTOK*DD];
// split transposed weights [N][K]
__device__ __nv_bfloat16 g_WqkvH[LL*QKVN*DD],  g_WqkvL[LL*QKVN*DD];
__device__ __nv_bfloat16 g_WoH  [LL*DD*DD],    g_WoL  [LL*DD*DD];
__device__ __nv_bfloat16 g_W1H  [LL*DFF_*DD],  g_W1L  [LL*DFF_*DD];
__device__ __nv_bfloat16 g_W2H  [LL*DD*DFF_],  g_W2L  [LL*DD*DFF_];
__device__ __nv_bfloat16 g_WpH  [DD*KPAT],     g_WpL  [DD*KPAT];
__device__ __nv_bfloat16 g_WprH [512*DD],      g_WprL [512*DD];

// ---------------- helpers ----------------
__device__ __forceinline__ uint32_t s2u(const void* p){
    return (uint32_t)__cvta_generic_to_shared(p);
}
__device__ __forceinline__ void ldsm4(uint32_t* r, uint32_t addr){
    asm volatile("ldmatrix.sync.aligned.m8n8.x4.shared.b16 {%0,%1,%2,%3}, [%4];"
        : "=r"(r[0]),"=r"(r[1]),"=r"(r[2]),"=r"(r[3]) : "r"(addr));
}
__device__ __forceinline__ void ldsm2(uint32_t* r, uint32_t addr){
    asm volatile("ldmatrix.sync.aligned.m8n8.x2.shared.b16 {%0,%1}, [%2];"
        : "=r"(r[0]),"=r"(r[1]) : "r"(addr));
}
__device__ __forceinline__ void cpa16(uint32_t d, const void* s, int sz){
    asm volatile("cp.async.cg.shared.global [%0], [%1], 16, %2;" :: "r"(d),"l"(s),"r"(sz));
}
__device__ __forceinline__ void mma_bf16(float* c, const uint32_t* a, const uint32_t* b){
    asm volatile(
        "mma.sync.aligned.m16n8k16.row.col.f32.bf16.bf16.f32 "
        "{%0,%1,%2,%3}, {%4,%5,%6,%7}, {%8,%9}, {%0,%1,%2,%3};\n"
        : "+f"(c[0]), "+f"(c[1]), "+f"(c[2]), "+f"(c[3])
        : "r"(a[0]), "r"(a[1]), "r"(a[2]), "r"(a[3]), "r"(b[0]), "r"(b[1]));
}
__device__ __forceinline__ void split_w(float v, __nv_bfloat16& h, __nv_bfloat16& l){
    h = __float2bfloat16(v);
    l = __float2bfloat16(v - __bfloat162float(h));
}

// ---------------- weight transpose + split: src[K,N] fp32 -> dst[N,K] bf16 hi/lo ----------------
__global__ void tsplit_kernel(const float* __restrict__ src, size_t srcStride,
                              __nv_bfloat16* __restrict__ dh, __nv_bfloat16* __restrict__ dl,
                              size_t dStride, int rowOff, int K, int N)
{
    __shared__ float tbuf[32][33];
    int l = blockIdx.z;
    const float* S = src + (size_t)l * srcStride;
    int n0 = blockIdx.x * 32, k0 = blockIdx.y * 32;
    for (int i = threadIdx.y; i < 32; i += 8)
        tbuf[i][threadIdx.x] = S[(size_t)(k0 + i) * N + n0 + threadIdx.x];
    __syncthreads();
    __nv_bfloat16* DH = dh + (size_t)l * dStride;
    __nv_bfloat16* DL = dl + (size_t)l * dStride;
    for (int i = threadIdx.y; i < 32; i += 8) {
        float v = tbuf[threadIdx.x][i];
        __nv_bfloat16 h, lo; split_w(v, h, lo);
        size_t idx = (size_t)(rowOff + n0 + i) * K + k0 + threadIdx.x;
        DH[idx] = h; DL[idx] = lo;
    }
}

__global__ void concat_bias_kernel(const float* __restrict__ bq, const float* __restrict__ bk,
                                   const float* __restrict__ bv, float* __restrict__ out)
{
    int i = blockIdx.x * 256 + threadIdx.x;
    if (i >= LL * QKVN) return;
    int l = i / QKVN, r = i % QKVN;
    const float* src = (r < 1024) ? bq : ((r < 2048) ? bk : bv);
    out[i] = src[l * 1024 + (r & 1023)];
}

// ---------------- im2col (writes split bf16) ----------------
__global__ void im2col_kernel(const float* __restrict__ imgs,
                              __nv_bfloat16* __restrict__ pH, __nv_bfloat16* __restrict__ pL)
{
    int idx = blockIdx.x * blockDim.x + threadIdx.x;
    const int total = BB * NTOK * KPAT;
    if (idx >= total) return;
    int k = idx % KPAT;
    int m = idx / KPAT;
    int n = m % NTOK;
    int b = m / NTOK;
    int h = n / HPP, w = n % HPP;
    int c = k / 256;
    int rem = k % 256;
    int p = rem / 16, q = rem % 16;
    float v = imgs[(((size_t)b * C_IN + c) * IMG + (h * PP + p)) * IMG + (w * PP + q)];
    __nv_bfloat16 hh, ll; split_w(v, hh, ll);
    pH[idx] = hh; pL[idx] = ll;
}

// ---------------- build x = [cls ; patch tokens] ----------------
__global__ void build_x_kernel(const float* __restrict__ res, const float* __restrict__ cls,
                               float* __restrict__ x)
{
    int idx = blockIdx.x * blockDim.x + threadIdx.x;
    const int total = BB * STOK * DD;
    if (idx >= total) return;
    int d = idx % DD;
    int r = idx / DD;
    int s = r % STOK;
    int b = r / STOK;
    x[idx] = (s == 0) ? cls[d] : res[((size_t)(b * NTOK + (s - 1))) * DD + d];
}

// ---------------- layernorm -> fp32 + split bf16 ----------------
__global__ void ln_kernel(const float* __restrict__ X, const float* __restrict__ w,
                          const float* __restrict__ bvec, float* __restrict__ Yf,
                          __nv_bfloat16* __restrict__ Yh, __nv_bfloat16* __restrict__ Yl)
{
    __shared__ float red[256];
    int row = blockIdx.x;
    int tid = threadIdx.x;
    const float* xr = X + (size_t)row * DD;
    float v[4];
    float s = 0.f;
#pragma unroll
    for (int i = 0; i < 4; i++) { v[i] = xr[tid + i * 256]; s += v[i]; }
    red[tid] = s; __syncthreads();
    for (int off = 128; off; off >>= 1) { if (tid < off) red[tid] += red[tid + off]; __syncthreads(); }
    float mu = red[0] * (1.f / DD);
    __syncthreads();
    float s2 = 0.f;
#pragma unroll
    for (int i = 0; i < 4; i++) { float d = v[i] - mu; s2 += d * d; }
    red[tid] = s2; __syncthreads();
    for (int off = 128; off; off >>= 1) { if (tid < off) red[tid] += red[tid + off]; __syncthreads(); }
    float inv = rsqrtf(red[0] * (1.f / DD) + 1e-5f);
#pragma unroll
    for (int i = 0; i < 4; i++) {
        int c = tid + i * 256;
        float y = (v[i] - mu) * inv * w[c] + bvec[c];
        Yf[(size_t)row * DD + c] = y;
        __nv_bfloat16 h, l; split_w(y, h, l);
        Yh[(size_t)row * DD + c] = h;
        Yl[(size_t)row * DD + c] = l;
    }
}

// ---------------- tensor-core GEMM ----------------
// A (split bf16 hi/lo) [M,K] row-major; B (split bf16 hi/lo) [N,K] row-major (pre-transposed)
// EPI 0: Cf = acc + bias; EPI 1: Cf = acc + bias + R; EPI 2: split(gelu(acc+bias)) -> Ch,Cl
template<int EPI>
__global__ __launch_bounds__(256)
void tgemm(const __nv_bfloat16* __restrict__ Ah, const __nv_bfloat16* __restrict__ Al,
           const __nv_bfloat16* __restrict__ Bh, const __nv_bfloat16* __restrict__ Bl,
           const float* __restrict__ bias, float* __restrict__ Cf,
           __nv_bfloat16* __restrict__ Ch, __nv_bfloat16* __restrict__ Cl,
           const float* __restrict__ R, int M, int Nn, int K)
{
    extern __shared__ __nv_bfloat16 sm[];
    __nv_bfloat16* SA_H = sm;
    __nv_bfloat16* SA_L = sm + 2 * 128 * 40;
    __nv_bfloat16* SB_H = sm + 4 * 128 * 40;
    __nv_bfloat16* SB_L = sm + 6 * 128 * 40;

    const int tid = threadIdx.x, warp = tid >> 5, lane = tid & 31;
    const int bm = blockIdx.y * 128, bn = blockIdx.x * 128;
    const int wm = warp >> 2, wn = warp & 3;

    float acc[4][4][4];
#pragma unroll
    for (int mt = 0; mt < 4; mt++)
#pragma unroll
        for (int nt = 0; nt < 4; nt++)
#pragma unroll
            for (int i = 0; i < 4; i++) acc[mt][nt][i] = 0.f;

    // global->smem loaders (cp.async, 16B chunks)
    const int lrow = tid >> 1, lc = (tid & 1) * 16;
    int aRow = bm + lrow;
    int asz = (aRow < M) ? 16 : 0;
    if (aRow >= M) aRow = M - 1;
    const __nv_bfloat16* agh = Ah + (size_t)aRow * K + lc;
    const __nv_bfloat16* agl = Al + (size_t)aRow * K + lc;
    const __nv_bfloat16* bgh = Bh + (size_t)(bn + lrow) * K + lc;
    const __nv_bfloat16* bgl = Bl + (size_t)(bn + lrow) * K + lc;
    const uint32_t stageB = 128 * 40 * 2;   // bytes per stage per matrix
    uint32_t dAH = s2u(&SA_H[lrow * 40 + lc]);
    uint32_t dAL = s2u(&SA_L[lrow * 40 + lc]);
    uint32_t dBH = s2u(&SB_H[lrow * 40 + lc]);
    uint32_t dBL = s2u(&SB_L[lrow * 40 + lc]);

    const int nT = K / 32;

    // prologue: stage 0
    {
        cpa16(dAH, agh, asz);          cpa16(dAH + 16, agh + 8, asz);
        cpa16(dAL, agl, asz);          cpa16(dAL + 16, agl + 8, asz);
        cpa16(dBH, bgh, 16);           cpa16(dBH + 16, bgh + 8, 16);
        cpa16(dBL, bgl, 16);           cpa16(dBL + 16, bgl + 8, 16);
        asm volatile("cp.async.commit_group;");
    }

    const int ar  = (lane & 15);
    const int ac0 = (lane >> 4) << 3;
    const int br  = (lane & 7);
    const int bc0 = ((lane >> 3) & 1) << 3;

    for (int t = 0; t < nT; t++) {
        if (t + 1 < nT) {
            int ko = (t + 1) * 32;
            uint32_t o = ((t + 1) & 1) * stageB;
            cpa16(dAH + o, agh + ko, asz);      cpa16(dAH + o + 16, agh + ko + 8, asz);
            cpa16(dAL + o, agl + ko, asz);      cpa16(dAL + o + 16, agl + ko + 8, asz);
            cpa16(dBH + o, bgh + ko, 16);       cpa16(dBH + o + 16, bgh + ko + 8, 16);
            cpa16(dBL + o, bgl + ko, 16);       cpa16(dBL + o + 16, bgl + ko + 8, 16);
            asm volatile("cp.async.commit_group;");
            asm volatile("cp.async.wait_group 1;");
        } else {
            asm volatile("cp.async.wait_group 0;");
        }
        __syncthreads();

        const int sOff = (t & 1) * (128 * 40);   // element offset of this stage
#pragma unroll
        for (int ks = 0; ks < 32; ks += 16) {
            uint32_t aH[4][4], aL[4][4];
#pragma unroll
            for (int mt = 0; mt < 4; mt++) {
                int r = wm * 64 + mt * 16 + ar;
                int c = ks + ac0;
                ldsm4(aH[mt], s2u(&SA_H[sOff + r * 40 + c]));
                ldsm4(aL[mt], s2u(&SA_L[sOff + r * 40 + c]));
            }
#pragma unroll
            for (int nt = 0; nt < 4; nt++) {
                int nr = wn * 32 + nt * 8 + br;
                int c = ks + bc0;
                uint32_t bH[2], bL[2];
                ldsm2(bH, s2u(&SB_H[sOff + nr * 40 + c]));
                ldsm2(bL, s2u(&SB_L[sOff + nr * 40 + c]));
#pragma unroll
                for (int mt = 0; mt < 4; mt++) mma_bf16(acc[mt][nt], aH[mt], bH);
#pragma unroll
                for (int mt = 0; mt < 4; mt++) mma_bf16(acc[mt][nt], aH[mt], bL);
#pragma unroll
                for (int mt = 0; mt < 4; mt++) mma_bf16(acc[mt][nt], aL[mt], bH);
            }
        }
        __syncthreads();
    }

    // epilogue
    const int g = lane >> 2, tq = lane & 3;
#pragma unroll
    for (int mt = 0; mt < 4; mt++) {
        int r0 = bm + wm * 64 + mt * 16 + g;
#pragma unroll
        for (int nt = 0; nt < 4; nt++) {
            int col = bn + wn * 32 + nt * 8 + 2 * tq;
            float b0 = bias[col], b1 = bias[col + 1];
#pragma unroll
            for (int hh = 0; hh < 2; hh++) {
                int row = r0 + hh * 8;
                if (row >= M) continue;
                float v0 = acc[mt][nt][hh * 2 + 0] + b0;
                float v1 = acc[mt][nt][hh * 2 + 1] + b1;
                if (EPI == 1) {
                    float2 r2 = *(const float2*)&R[(size_t)row * Nn + col];
                    v0 += r2.x; v1 += r2.y;
                }
                if (EPI == 2) {
                    v0 = 0.5f * v0 * (1.f + erff(v0 * 0.70710678118654752f));
                    v1 = 0.5f * v1 * (1.f + erff(v1 * 0.70710678118654752f));
                    __nv_bfloat16 h0, l0, h1, l1;
                    split_w(v0, h0, l0); split_w(v1, h1, l1);
                    __nv_bfloat162 ph; ph.x = h0; ph.y = h1;
                    __nv_bfloat162 pl; pl.x = l0; pl.y = l1;
                    *(__nv_bfloat162*)&Ch[(size_t)row * Nn + col] = ph;
                    *(__nv_bfloat162*)&Cl[(size_t)row * Nn + col] = pl;
                } else {
                    float2 o; o.x = v0; o.y = v1;
                    *(float2*)&Cf[(size_t)row * Nn + col] = o;
                }
            }
        }
    }
}

// ---------------- fused attention (reads combined qkv, writes split o) ----------------
__global__ __launch_bounds__(256)
void attn_kernel(const float* __restrict__ qkv,
                 __nv_bfloat16* __restrict__ oH, __nv_bfloat16* __restrict__ oL)
{
    __shared__ float sQ[8][64];
    __shared__ float sKV[64][65];
    __shared__ float sP[8][257];

    const int i0 = blockIdx.x * 8;
    const int h  = blockIdx.y;
    const int b  = blockIdx.z;
    const int warp = threadIdx.x >> 5;
    const int lane = threadIdx.x & 31;

    const float decay = logf(1.f - exp2f(-1.f - (float)h));

    for (int idx = threadIdx.x; idx < 8 * 64; idx += 256) {
        int r = idx >> 6, d = idx & 63;
        int i = i0 + r;
        sQ[r][d] = (i < STOK) ? qkv[((size_t)(b * STOK + i)) * QKVN + h * HD_ + d] * 0.125f : 0.f;
    }

    const int my_i = i0 + warp;
    int yq = 0, xq = 0;
    if (my_i > 0) { yq = (my_i - 1) >> 4; xq = (my_i - 1) & 15; }

    for (int j0 = 0; j0 < STOK; j0 += 64) {
        int rows = min(64, STOK - j0);
        __syncthreads();
        for (int idx = threadIdx.x; idx < rows * 64; idx += 256) {
            int r = idx >> 6, d = idx & 63;
            sKV[r][d] = qkv[((size_t)(b * STOK + j0 + r)) * QKVN + 1024 + h * HD_ + d];
        }
        __syncthreads();
        if (my_i < STOK) {
            for (int jj = lane; jj < rows; jj += 32) {
                float s = 0.f;
#pragma unroll
                for (int d = 0; d < 64; d++) s += sQ[warp][d] * sKV[jj][d];
                int j = j0 + jj;
                if (my_i > 0 && j > 0) {
                    int yk = (j - 1) >> 4, xk = (j - 1) & 15;
                    s += decay * (float)(abs(yq - yk) + abs(xq - xk));
                }
                sP[warp][j] = s;
            }
        }
    }

    if (my_i < STOK) {
        float m = -1e30f;
        for (int j = lane; j < STOK; j += 32) m = fmaxf(m, sP[warp][j]);
#pragma unroll
        for (int o = 16; o; o >>= 1) m = fmaxf(m, __shfl_xor_sync(0xffffffffu, m, o));
        float sum = 0.f;
        for (int j = lane; j < STOK; j += 32) {
            float e = __expf(sP[warp][j] - m);
            sP[warp][j] = e;
            sum += e;
        }
#pragma unroll
        for (int o = 16; o; o >>= 1) sum += __shfl_xor_sync(0xffffffffu, sum, o);
        float inv = 1.f / sum;
        for (int j = lane; j < STOK; j += 32) sP[warp][j] *= inv;
    }

    float acc0 = 0.f, acc1 = 0.f;
    for (int j0 = 0; j0 < STOK; j0 += 64) {
        int rows = min(64, STOK - j0);
        __syncthreads();
        for (int idx = threadIdx.x; idx < rows * 64; idx += 256) {
            int r = idx >> 6, d = idx & 63;
            sKV[r][d] = qkv[((size_t)(b * STOK + j0 + r)) * QKVN + 2048 + h * HD_ + d];
        }
        __syncthreads();
        if (my_i < STOK) {
            for (int jj = 0; jj < rows; jj++) {
                float p = sP[warp][j0 + jj];
                acc0 += p * sKV[jj][lane];
                acc1 += p * sKV[jj][lane + 32];
            }
        }
    }
    if (my_i < STOK) {
        size_t base = ((size_t)(b * STOK + my_i)) * DD + h * HD_;
        __nv_bfloat16 h0, l0, h1, l1;
        split_w(acc0, h0, l0); split_w(acc1, h1, l1);
        oH[base + lane]      = h0; oL[base + lane]      = l0;
        oH[base + lane + 32] = h1; oL[base + lane + 32] = l1;
    }
}

// ---------------- PGSA gating + residual (writes split tok) ----------------
__global__ void pgsa_kernel(const float* __restrict__ XF, const float* __restrict__ RES,
                            __nv_bfloat16* __restrict__ tokH, __nv_bfloat16* __restrict__ tokL)
{
    __shared__ float red[256];
    int d = blockIdx.x % DD;
    int b = blockIdx.x / DD;
    int n = threadIdx.x;

    float t = XF[((size_t)(b * STOK) + 1 + n) * DD + d];

    red[n] = t; __syncthreads();
    for (int off = 128; off; off >>= 1) { if (n < off) red[n] += red[n + off]; __syncthreads(); }
    float mu = red[0] * (1.f / NTOK);
    __syncthreads();

    float dm = t - mu;
    float xm2 = dm * dm;
    red[n] = xm2; __syncthreads();
    for (int off = 128; off; off >>= 1) { if (n < off) red[n] += red[n + off]; __syncthreads(); }
    float s2 = red[0];

    float y = xm2 / (4.f * (s2 * (1.f / 255.f) + 1e-4f)) + 0.5f;
    float sig = 1.f / (1.f + __expf(-y));
    float v = t * sig + RES[((size_t)(b * NTOK + n)) * DD + d];
    __nv_bfloat16 hh, ll; split_w(v, hh, ll);
    size_t o = ((size_t)(b * NTOK + n)) * DD + d;
    tokH[o] = hh; tokL[o] = ll;
}

// ---------------- unpatchify ----------------
__global__ void unpatch_kernel(const float* __restrict__ pred, float* __restrict__ out)
{
    int idx = blockIdx.x * blockDim.x + threadIdx.x;
    const int total = BB * 2 * IMG * IMG;
    if (idx >= total) return;
    int r  = idx % (2 * IMG * IMG);
    int b  = idx / (2 * IMG * IMG);
    int c  = r / (IMG * IMG);
    int r2 = r % (IMG * IMG);
    int y  = r2 / IMG, x = r2 % IMG;
    int h = y >> 4, p = y & 15, w = x >> 4, q = x & 15;
    out[idx] = pred[((size_t)(b * NTOK + h * HPP + w)) * (PP * PP * 2) + ((p * 16 + q) * 2 + c)];
}

// ---------------- host orchestration ----------------
#define GEMM_SMEM (8 * 128 * 40 * 2)   // 81920 bytes

static inline void launch_gemm(int epi,
                               const __nv_bfloat16* Ah, const __nv_bfloat16* Al,
                               const __nv_bfloat16* Bh, const __nv_bfloat16* Bl,
                               const float* bias, float* Cf,
                               __nv_bfloat16* Ch, __nv_bfloat16* Cl,
                               const float* R, int M, int Nn, int K)
{
    dim3 grid(Nn / 128, (M + 127) / 128);
    if (epi == 0)      tgemm<0><<<grid, 256, GEMM_SMEM>>>(Ah, Al, Bh, Bl, bias, Cf, Ch, Cl, R, M, Nn, K);
    else if (epi == 1) tgemm<1><<<grid, 256, GEMM_SMEM>>>(Ah, Al, Bh, Bl, bias, Cf, Ch, Cl, R, M, Nn, K);
    else               tgemm<2><<<grid, 256, GEMM_SMEM>>>(Ah, Al, Bh, Bl, bias, Cf, Ch, Cl, R, M, Nn, K);
}

extern "C" void kernel_launch(void* const* d_in, const int* in_sizes, int n_in,
                              void* d_out, int out_size)
{
    const float* imgs     = (const float*)d_in[0];
    const float* patch_w  = (const float*)d_in[1];
    const float* patch_b  = (const float*)d_in[2];
    const float* cls_tok  = (const float*)d_in[3];
    const float* ln1_w    = (const float*)d_in[4];
    const float* ln1_b    = (const float*)d_in[5];
    const float* wq       = (const float*)d_in[6];
    const float* wk       = (const float*)d_in[7];
    const float* wv       = (const float*)d_in[8];
    const float* bq       = (const float*)d_in[9];
    const float* bk       = (const float*)d_in[10];
    const float* bv       = (const float*)d_in[11];
    const float* wo       = (const float*)d_in[12];
    const float* bo       = (const float*)d_in[13];
    const float* ln2_w    = (const float*)d_in[14];
    const float* ln2_b    = (const float*)d_in[15];
    const float* w1       = (const float*)d_in[16];
    const float* b1       = (const float*)d_in[17];
    const float* w2       = (const float*)d_in[18];
    const float* b2       = (const float*)d_in[19];
    const float* normf_w  = (const float*)d_in[20];
    const float* normf_b  = (const float*)d_in[21];
    const float* enpred_w = (const float*)d_in[22];
    const float* enpred_b = (const float*)d_in[23];

    cudaFuncSetAttribute(tgemm<0>, cudaFuncAttributeMaxDynamicSharedMemorySize, GEMM_SMEM);
    cudaFuncSetAttribute(tgemm<1>, cudaFuncAttributeMaxDynamicSharedMemorySize, GEMM_SMEM);
    cudaFuncSetAttribute(tgemm<2>, cudaFuncAttributeMaxDynamicSharedMemorySize, GEMM_SMEM);

    float *x, *h, *qkv, *res, *pred, *bqkv;
    cudaGetSymbolAddress((void**)&x,    g_x);
    cudaGetSymbolAddress((void**)&h,    g_h);
    cudaGetSymbolAddress((void**)&qkv,  g_qkv);
    cudaGetSymbolAddress((void**)&res,  g_res);
    cudaGetSymbolAddress((void**)&pred, g_pred);
    cudaGetSymbolAddress((void**)&bqkv, g_bqkv);

    __nv_bfloat16 *hH,*hL,*oH,*oL,*mlpH,*mlpL,*pH,*pL,*tokH,*tokL;
    cudaGetSymbolAddress((void**)&hH,   g_hH);   cudaGetSymbolAddress((void**)&hL,   g_hL);
    cudaGetSymbolAddress((void**)&oH,   g_oH);   cudaGetSymbolAddress((void**)&oL,   g_oL);
    cudaGetSymbolAddress((void**)&mlpH, g_mlpH); cudaGetSymbolAddress((void**)&mlpL, g_mlpL);
    cudaGetSymbolAddress((void**)&pH,   g_pH);   cudaGetSymbolAddress((void**)&pL,   g_pL);
    cudaGetSymbolAddress((void**)&tokH, g_tokH); cudaGetSymbolAddress((void**)&tokL, g_tokL);

    __nv_bfloat16 *WqkvH,*WqkvL,*WoH,*WoL,*W1H,*W1L,*W2H,*W2L,*WpH,*WpL,*WprH,*WprL;
    cudaGetSymbolAddress((void**)&WqkvH, g_WqkvH); cudaGetSymbolAddress((void**)&WqkvL, g_WqkvL);
    cudaGetSymbolAddress((void**)&WoH,   g_WoH);   cudaGetSymbolAddress((void**)&WoL,   g_WoL);
    cudaGetSymbolAddress((void**)&W1H,   g_W1H);   cudaGetSymbolAddress((void**)&W1L,   g_W1L);
    cudaGetSymbolAddress((void**)&W2H,   g_W2H);   cudaGetSymbolAddress((void**)&W2L,   g_W2L);
    cudaGetSymbolAddress((void**)&WpH,   g_WpH);   cudaGetSymbolAddress((void**)&WpL,   g_WpL);
    cudaGetSymbolAddress((void**)&WprH,  g_WprH);  cudaGetSymbolAddress((void**)&WprL,  g_WprL);

    const int Mtok = BB * STOK;   // 2056
    const int Mpat = BB * NTOK;   // 2048
    dim3 tb(32, 8);

    // ---- weight preprocessing (transpose + split), every call ----
    tsplit_kernel<<<dim3(32, 32, LL), tb>>>(wq, (size_t)DD * DD, WqkvH, WqkvL, (size_t)QKVN * DD, 0,    DD, DD);
    tsplit_kernel<<<dim3(32, 32, LL), tb>>>(wk, (size_t)DD * DD, WqkvH, WqkvL, (size_t)QKVN * DD, 1024, DD, DD);
    tsplit_kernel<<<dim3(32, 32, LL), tb>>>(wv, (size_t)DD * DD, WqkvH, WqkvL, (size_t)QKVN * DD, 2048, DD, DD);
    tsplit_kernel<<<dim3(32, 32, LL), tb>>>(wo, (size_t)DD * DD, WoH, WoL, (size_t)DD * DD, 0, DD, DD);
    tsplit_kernel<<<dim3(128, 32, LL), tb>>>(w1, (size_t)DD * DFF_, W1H, W1L, (size_t)DFF_ * DD, 0, DD, DFF_);
    tsplit_kernel<<<dim3(32, 128, LL), tb>>>(w2, (size_t)DFF_ * DD, W2H, W2L, (size_t)DD * DFF_, 0, DFF_, DD);
    tsplit_kernel<<<dim3(32, 16, 1), tb>>>(patch_w, 0, WpH, WpL, 0, 0, KPAT, DD);
    tsplit_kernel<<<dim3(16, 32, 1), tb>>>(enpred_w, 0, WprH, WprL, 0, 0, DD, 512);
    concat_bias_kernel<<<(LL * QKVN + 255) / 256, 256>>>(bq, bk, bv, bqkv);

    // ---- patch embed ----
    im2col_kernel<<<(Mpat * KPAT + 255) / 256, 256>>>(imgs, pH, pL);
    launch_gemm(0, pH, pL, WpH, WpL, patch_b, res, nullptr, nullptr, nullptr, Mpat, DD, KPAT);
    build_x_kernel<<<(BB * STOK * DD + 255) / 256, 256>>>(res, cls_tok, x);

    for (int i = 0; i < LL; i++) {
        const size_t bOff = (size_t)i * DD;
        // attention block
        ln_kernel<<<Mtok, 256>>>(x, ln1_w + bOff, ln1_b + bOff, h, hH, hL);
        launch_gemm(0, hH, hL, WqkvH + (size_t)i * QKVN * DD, WqkvL + (size_t)i * QKVN * DD,
                    bqkv + (size_t)i * QKVN, qkv, nullptr, nullptr, nullptr, Mtok, QKVN, DD);
        attn_kernel<<<dim3((STOK + 7) / 8, NHH, BB), 256>>>(qkv, oH, oL);
        launch_gemm(1, oH, oL, WoH + (size_t)i * DD * DD, WoL + (size_t)i * DD * DD,
                    bo + bOff, x, nullptr, nullptr, x, Mtok, DD, DD);
        // MLP block
        ln_kernel<<<Mtok, 256>>>(x, ln2_w + bOff, ln2_b + bOff, h, hH, hL);
        launch_gemm(2, hH, hL, W1H + (size_t)i * DFF_ * DD, W1L + (size_t)i * DFF_ * DD,
                    b1 + (size_t)i * DFF_, nullptr, mlpH, mlpL, nullptr, Mtok, DFF_, DD);
        launch_gemm(1, mlpH, mlpL, W2H + (size_t)i * DD * DFF_, W2L + (size_t)i * DD * DFF_,
                    b2 + bOff, x, nullptr, nullptr, x, Mtok, DD, DFF_);
    }

    // ---- tail ----
    ln_kernel<<<Mtok, 256>>>(x, normf_w, normf_b, h, hH, hL);
    pgsa_kernel<<<BB * DD, 256>>>(h, res, tokH, tokL);
    launch_gemm(0, tokH, tokL, WprH, WprL, enpred_b, pred, nullptr, nullptr, nullptr, Mpat, 512, DD);
    unpatch_kernel<<<(out_size + 255) / 256, 256>>>(pred, (float*)d_out);
}

// round 6
// speedup vs baseline: 2.5983x; 1.0948x over previous
#include <cuda_runtime.h>
#include <cuda_bf16.h>
#include <math.h>
#include <stdint.h>

// ---------------- problem constants ----------------
#define BB    8
#define C_IN  2
#define IMG   256
#define PP    16
#define DD    1024
#define LL    8
#define NHH   16
#define DFF_  4096
#define HPP   16
#define NTOK  256
#define STOK  257
#define HD_   64
#define KPAT  512
#define QKVN  3072

// ---------------- static scratch (no allocations) ----------------
__device__ float g_x    [BB * STOK * DD];
__device__ float g_h    [BB * STOK * DD];
__device__ float g_qkv  [BB * STOK * QKVN];
__device__ float g_res  [BB * NTOK * DD];
__device__ float g_pred [BB * NTOK * (PP*PP*2)];
__device__ float g_bqkv [LL * QKVN];
__device__ __nv_bfloat16 g_hH[BB*STOK*DD],   g_hL[BB*STOK*DD];
__device__ __nv_bfloat16 g_oH[BB*STOK*DD],   g_oL[BB*STOK*DD];
__device__ __nv_bfloat16 g_mlpH[BB*STOK*DFF_], g_mlpL[BB*STOK*DFF_];
__device__ __nv_bfloat16 g_pH[BB*NTOK*KPAT], g_pL[BB*NTOK*KPAT];
__device__ __nv_bfloat16 g_tokH[BB*NTOK*DD], g_tokL[BB*NTOK*DD];
__device__ __nv_bfloat16 g_WqkvH[LL*QKVN*DD],  g_WqkvL[LL*QKVN*DD];
__device__ __nv_bfloat16 g_WoH  [LL*DD*DD],    g_WoL  [LL*DD*DD];
__device__ __nv_bfloat16 g_W1H  [LL*DFF_*DD],  g_W1L  [LL*DFF_*DD];
__device__ __nv_bfloat16 g_W2H  [LL*DD*DFF_],  g_W2L  [LL*DD*DFF_];
__device__ __nv_bfloat16 g_WpH  [DD*KPAT],     g_WpL  [DD*KPAT];
__device__ __nv_bfloat16 g_WprH [512*DD],      g_WprL [512*DD];

// ---------------- helpers ----------------
__device__ __forceinline__ uint32_t s2u(const void* p){
    return (uint32_t)__cvta_generic_to_shared(p);
}
__device__ __forceinline__ void ldsm4(uint32_t* r, uint32_t addr){
    asm volatile("ldmatrix.sync.aligned.m8n8.x4.shared.b16 {%0,%1,%2,%3}, [%4];"
        : "=r"(r[0]),"=r"(r[1]),"=r"(r[2]),"=r"(r[3]) : "r"(addr));
}
__device__ __forceinline__ void cpa16(uint32_t d, const void* s, int sz){
    asm volatile("cp.async.cg.shared.global [%0], [%1], 16, %2;" :: "r"(d),"l"(s),"r"(sz));
}
__device__ __forceinline__ void mma_bf16(float* c, const uint32_t* a, const uint32_t* b){
    asm volatile(
        "mma.sync.aligned.m16n8k16.row.col.f32.bf16.bf16.f32 "
        "{%0,%1,%2,%3}, {%4,%5,%6,%7}, {%8,%9}, {%0,%1,%2,%3};\n"
        : "+f"(c[0]), "+f"(c[1]), "+f"(c[2]), "+f"(c[3])
        : "r"(a[0]), "r"(a[1]), "r"(a[2]), "r"(a[3]), "r"(b[0]), "r"(b[1]));
}
__device__ __forceinline__ void split_w(float v, __nv_bfloat16& h, __nv_bfloat16& l){
    h = __float2bfloat16(v);
    l = __float2bfloat16(v - __bfloat162float(h));
}

// ---------------- weight transpose + split: src[K,N] fp32 -> dst[N,K] bf16 hi/lo ----------------
__global__ void tsplit_kernel(const float* __restrict__ src, size_t srcStride,
                              __nv_bfloat16* __restrict__ dh, __nv_bfloat16* __restrict__ dl,
                              size_t dStride, int rowOff, int K, int N)
{
    __shared__ float tbuf[32][33];
    int l = blockIdx.z;
    const float* S = src + (size_t)l * srcStride;
    int n0 = blockIdx.x * 32, k0 = blockIdx.y * 32;
    for (int i = threadIdx.y; i < 32; i += 8)
        tbuf[i][threadIdx.x] = S[(size_t)(k0 + i) * N + n0 + threadIdx.x];
    __syncthreads();
    __nv_bfloat16* DH = dh + (size_t)l * dStride;
    __nv_bfloat16* DL = dl + (size_t)l * dStride;
    for (int i = threadIdx.y; i < 32; i += 8) {
        float v = tbuf[threadIdx.x][i];
        __nv_bfloat16 h, lo; split_w(v, h, lo);
        size_t idx = (size_t)(rowOff + n0 + i) * K + k0 + threadIdx.x;
        DH[idx] = h; DL[idx] = lo;
    }
}

__global__ void concat_bias_kernel(const float* __restrict__ bq, const float* __restrict__ bk,
                                   const float* __restrict__ bv, float* __restrict__ out)
{
    int i = blockIdx.x * 256 + threadIdx.x;
    if (i >= LL * QKVN) return;
    int l = i / QKVN, r = i % QKVN;
    const float* src = (r < 1024) ? bq : ((r < 2048) ? bk : bv);
    out[i] = src[l * 1024 + (r & 1023)];
}

// ---------------- im2col (writes split bf16) ----------------
__global__ void im2col_kernel(const float* __restrict__ imgs,
                              __nv_bfloat16* __restrict__ pH, __nv_bfloat16* __restrict__ pL)
{
    int idx = blockIdx.x * blockDim.x + threadIdx.x;
    const int total = BB * NTOK * KPAT;
    if (idx >= total) return;
    int k = idx % KPAT;
    int m = idx / KPAT;
    int n = m % NTOK;
    int b = m / NTOK;
    int h = n / HPP, w = n % HPP;
    int c = k / 256;
    int rem = k % 256;
    int p = rem / 16, q = rem % 16;
    float v = imgs[(((size_t)b * C_IN + c) * IMG + (h * PP + p)) * IMG + (w * PP + q)];
    __nv_bfloat16 hh, ll; split_w(v, hh, ll);
    pH[idx] = hh; pL[idx] = ll;
}

// ---------------- build x ----------------
__global__ void build_x_kernel(const float* __restrict__ res, const float* __restrict__ cls,
                               float* __restrict__ x)
{
    int idx = blockIdx.x * blockDim.x + threadIdx.x;
    const int total = BB * STOK * DD;
    if (idx >= total) return;
    int d = idx % DD;
    int r = idx / DD;
    int s = r % STOK;
    int b = r / STOK;
    x[idx] = (s == 0) ? cls[d] : res[((size_t)(b * NTOK + (s - 1))) * DD + d];
}

// ---------------- layernorm -> optional fp32 + optional split bf16 ----------------
__global__ void ln_kernel(const float* __restrict__ X, const float* __restrict__ w,
                          const float* __restrict__ bvec, float* __restrict__ Yf,
                          __nv_bfloat16* __restrict__ Yh, __nv_bfloat16* __restrict__ Yl)
{
    __shared__ float red[256];
    int row = blockIdx.x;
    int tid = threadIdx.x;
    const float* xr = X + (size_t)row * DD;
    float v[4];
    float s = 0.f;
#pragma unroll
    for (int i = 0; i < 4; i++) { v[i] = xr[tid + i * 256]; s += v[i]; }
    red[tid] = s; __syncthreads();
    for (int off = 128; off; off >>= 1) { if (tid < off) red[tid] += red[tid + off]; __syncthreads(); }
    float mu = red[0] * (1.f / DD);
    __syncthreads();
    float s2 = 0.f;
#pragma unroll
    for (int i = 0; i < 4; i++) { float d = v[i] - mu; s2 += d * d; }
    red[tid] = s2; __syncthreads();
    for (int off = 128; off; off >>= 1) { if (tid < off) red[tid] += red[tid + off]; __syncthreads(); }
    float inv = rsqrtf(red[0] * (1.f / DD) + 1e-5f);
#pragma unroll
    for (int i = 0; i < 4; i++) {
        int c = tid + i * 256;
        float y = (v[i] - mu) * inv * w[c] + bvec[c];
        if (Yf) Yf[(size_t)row * DD + c] = y;
        if (Yh) {
            __nv_bfloat16 h, l; split_w(y, h, l);
            Yh[(size_t)row * DD + c] = h;
            Yl[(size_t)row * DD + c] = l;
        }
    }
}

// ---------------- tensor-core GEMM (split bf16, cp.async 2-stage, ldsm) ----------------
template<int EPI>
__global__ __launch_bounds__(256)
void tgemm(const __nv_bfloat16* __restrict__ Ah, const __nv_bfloat16* __restrict__ Al,
           const __nv_bfloat16* __restrict__ Bh, const __nv_bfloat16* __restrict__ Bl,
           const float* __restrict__ bias, float* __restrict__ Cf,
           __nv_bfloat16* __restrict__ Ch, __nv_bfloat16* __restrict__ Cl,
           const float* __restrict__ R, int M, int Nn, int K)
{
    extern __shared__ __nv_bfloat16 sm[];
    __nv_bfloat16* SA_H = sm;
    __nv_bfloat16* SA_L = sm + 2 * 128 * 40;
    __nv_bfloat16* SB_H = sm + 4 * 128 * 40;
    __nv_bfloat16* SB_L = sm + 6 * 128 * 40;

    const int tid = threadIdx.x, warp = tid >> 5, lane = tid & 31;
    const int bm = blockIdx.y * 128, bn = blockIdx.x * 128;
    const int wm = warp >> 2, wn = warp & 3;

    float acc[4][4][4];
#pragma unroll
    for (int mt = 0; mt < 4; mt++)
#pragma unroll
        for (int nt = 0; nt < 4; nt++)
#pragma unroll
            for (int i = 0; i < 4; i++) acc[mt][nt][i] = 0.f;

    const int lrow = tid >> 1, lc = (tid & 1) * 16;
    int aRow = bm + lrow;
    int asz = (aRow < M) ? 16 : 0;
    if (aRow >= M) aRow = M - 1;
    const __nv_bfloat16* agh = Ah + (size_t)aRow * K + lc;
    const __nv_bfloat16* agl = Al + (size_t)aRow * K + lc;
    const __nv_bfloat16* bgh = Bh + (size_t)(bn + lrow) * K + lc;
    const __nv_bfloat16* bgl = Bl + (size_t)(bn + lrow) * K + lc;
    const uint32_t stageB = 128 * 40 * 2;
    uint32_t dAH = s2u(&SA_H[lrow * 40 + lc]);
    uint32_t dAL = s2u(&SA_L[lrow * 40 + lc]);
    uint32_t dBH = s2u(&SB_H[lrow * 40 + lc]);
    uint32_t dBL = s2u(&SB_L[lrow * 40 + lc]);

    const int nT = K / 32;

    {
        cpa16(dAH, agh, asz);          cpa16(dAH + 16, agh + 8, asz);
        cpa16(dAL, agl, asz);          cpa16(dAL + 16, agl + 8, asz);
        cpa16(dBH, bgh, 16);           cpa16(dBH + 16, bgh + 8, 16);
        cpa16(dBL, bgl, 16);           cpa16(dBL + 16, bgl + 8, 16);
        asm volatile("cp.async.commit_group;");
    }

    const int ar  = (lane & 15);
    const int ac0 = (lane >> 4) << 3;
    // B ldsm4 addressing: pairs of nt
    const int brr = ((lane >> 4) << 3) + (lane & 7);  // row within 16-row pair block
    const int bcc = ((lane >> 3) & 1) << 3;           // k offset 0/8

    for (int t = 0; t < nT; t++) {
        if (t + 1 < nT) {
            int ko = (t + 1) * 32;
            uint32_t o = ((t + 1) & 1) * stageB;
            cpa16(dAH + o, agh + ko, asz);      cpa16(dAH + o + 16, agh + ko + 8, asz);
            cpa16(dAL + o, agl + ko, asz);      cpa16(dAL + o + 16, agl + ko + 8, asz);
            cpa16(dBH + o, bgh + ko, 16);       cpa16(dBH + o + 16, bgh + ko + 8, 16);
            cpa16(dBL + o, bgl + ko, 16);       cpa16(dBL + o + 16, bgl + ko + 8, 16);
            asm volatile("cp.async.commit_group;");
            asm volatile("cp.async.wait_group 1;");
        } else {
            asm volatile("cp.async.wait_group 0;");
        }
        __syncthreads();

        const int sOff = (t & 1) * (128 * 40);
#pragma unroll
        for (int ks = 0; ks < 32; ks += 16) {
            uint32_t aH[4][4], aL[4][4];
#pragma unroll
            for (int mt = 0; mt < 4; mt++) {
                int r = wm * 64 + mt * 16 + ar;
                int c = ks + ac0;
                ldsm4(aH[mt], s2u(&SA_H[sOff + r * 40 + c]));
                ldsm4(aL[mt], s2u(&SA_L[sOff + r * 40 + c]));
            }
#pragma unroll
            for (int ntp = 0; ntp < 2; ntp++) {
                int nr = wn * 32 + ntp * 16 + brr;
                int c  = ks + bcc;
                uint32_t bH4[4], bL4[4];
                ldsm4(bH4, s2u(&SB_H[sOff + nr * 40 + c]));
                ldsm4(bL4, s2u(&SB_L[sOff + nr * 40 + c]));
#pragma unroll
                for (int n2 = 0; n2 < 2; n2++) {
                    int nt = ntp * 2 + n2;
#pragma unroll
                    for (int mt = 0; mt < 4; mt++) mma_bf16(acc[mt][nt], aH[mt], &bH4[n2*2]);
#pragma unroll
                    for (int mt = 0; mt < 4; mt++) mma_bf16(acc[mt][nt], aH[mt], &bL4[n2*2]);
#pragma unroll
                    for (int mt = 0; mt < 4; mt++) mma_bf16(acc[mt][nt], aL[mt], &bH4[n2*2]);
                }
            }
        }
        __syncthreads();
    }

    const int g = lane >> 2, tq = lane & 3;
#pragma unroll
    for (int mt = 0; mt < 4; mt++) {
        int r0 = bm + wm * 64 + mt * 16 + g;
#pragma unroll
        for (int nt = 0; nt < 4; nt++) {
            int col = bn + wn * 32 + nt * 8 + 2 * tq;
            float b0 = bias[col], b1 = bias[col + 1];
#pragma unroll
            for (int hh = 0; hh < 2; hh++) {
                int row = r0 + hh * 8;
                if (row >= M) continue;
                float v0 = acc[mt][nt][hh * 2 + 0] + b0;
                float v1 = acc[mt][nt][hh * 2 + 1] + b1;
                if (EPI == 1) {
                    float2 r2 = *(const float2*)&R[(size_t)row * Nn + col];
                    v0 += r2.x; v1 += r2.y;
                }
                if (EPI == 2) {
                    v0 = 0.5f * v0 * (1.f + erff(v0 * 0.70710678118654752f));
                    v1 = 0.5f * v1 * (1.f + erff(v1 * 0.70710678118654752f));
                    __nv_bfloat16 h0, l0, h1, l1;
                    split_w(v0, h0, l0); split_w(v1, h1, l1);
                    __nv_bfloat162 ph; ph.x = h0; ph.y = h1;
                    __nv_bfloat162 pl; pl.x = l0; pl.y = l1;
                    *(__nv_bfloat162*)&Ch[(size_t)row * Nn + col] = ph;
                    *(__nv_bfloat162*)&Cl[(size_t)row * Nn + col] = pl;
                } else {
                    float2 o; o.x = v0; o.y = v1;
                    *(float2*)&Cf[(size_t)row * Nn + col] = o;
                }
            }
        }
    }
}

// ---------------- fused attention, d-split decomposition ----------------
// block: 256 threads (8 warps). 8 query rows per block.
// warp w owns head-dim slice [8w, 8w+8). lane = (q = lane>>2, jg = lane&3).
__global__ __launch_bounds__(256)
void attn_kernel(const float* __restrict__ qkv,
                 __nv_bfloat16* __restrict__ oH, __nv_bfloat16* __restrict__ oL)
{
    __shared__ float sQ[8][64];
    __shared__ float sKV[64][68];
    __shared__ float sP[8][324];
    __shared__ float sPart[8][64][9];   // [warp][jj][q]

    const int i0 = blockIdx.x * 8;
    const int h  = blockIdx.y;
    const int b  = blockIdx.z;
    const int tid = threadIdx.x;
    const int w = tid >> 5, lane = tid & 31;
    const int q = lane >> 2, jg = lane & 3;

    const float decay = logf(1.f - exp2f(-1.f - (float)h));

    // load Q rows (pre-scaled)
    for (int idx = tid; idx < 512; idx += 256) {
        int r = idx >> 6, d = idx & 63;
        int i = i0 + r;
        sQ[r][d] = (i < STOK) ? qkv[((size_t)(b*STOK + i))*QKVN + h*HD_ + d] * 0.125f : 0.f;
    }
    __syncthreads();

    const float4 Qr0 = *(const float4*)&sQ[q][w*8];
    const float4 Qr1 = *(const float4*)&sQ[q][w*8 + 4];

    // ---- pass 1: logits ----
    for (int j0 = 0; j0 < STOK; j0 += 64) {
        int rows = min(64, STOK - j0);
        __syncthreads();
        for (int lin = tid; lin < 1024; lin += 256) {
            int j = lin >> 4, d4 = (lin & 15) << 2;
            float4 v = make_float4(0.f, 0.f, 0.f, 0.f);
            if (j < rows)
                v = *(const float4*)&qkv[((size_t)(b*STOK + j0 + j))*QKVN + 1024 + h*HD_ + d4];
            *(float4*)&sKV[j][d4] = v;
        }
        __syncthreads();
#pragma unroll
        for (int jjg = 0; jjg < 16; jjg++) {
            int jj = jjg * 4 + jg;
            float4 k0 = *(const float4*)&sKV[jj][w*8];
            float4 k1 = *(const float4*)&sKV[jj][w*8 + 4];
            float s = k0.x*Qr0.x + k0.y*Qr0.y + k0.z*Qr0.z + k0.w*Qr0.w
                    + k1.x*Qr1.x + k1.y*Qr1.y + k1.z*Qr1.z + k1.w*Qr1.w;
            sPart[w][jj][q] = s;
        }
        __syncthreads();
        for (int p = tid; p < 512; p += 256) {
            int qq = p & 7, jj = p >> 3;
            if (jj >= rows) continue;
            float s = 0.f;
#pragma unroll
            for (int ww = 0; ww < 8; ww++) s += sPart[ww][jj][qq];
            int i = i0 + qq, j = j0 + jj;
            if (i > 0 && j > 0) {
                int yq2 = (i - 1) >> 4, xq2 = (i - 1) & 15;
                int yk  = (j - 1) >> 4, xk  = (j - 1) & 15;
                s += decay * (float)(abs(yq2 - yk) + abs(xq2 - xk));
            }
            sP[qq][j] = s;
        }
    }
    __syncthreads();

    // ---- softmax: warp w handles query row w ----
    {
        float m = -1e30f;
        for (int j = lane; j < STOK; j += 32) m = fmaxf(m, sP[w][j]);
#pragma unroll
        for (int o = 16; o; o >>= 1) m = fmaxf(m, __shfl_xor_sync(0xffffffffu, m, o));
        float sum = 0.f;
        for (int j = lane; j < STOK; j += 32) {
            float e = __expf(sP[w][j] - m);
            sP[w][j] = e;
            sum += e;
        }
#pragma unroll
        for (int o = 16; o; o >>= 1) sum += __shfl_xor_sync(0xffffffffu, sum, o);
        float inv = 1.f / sum;
        for (int j = lane; j < STOK; j += 32) sP[w][j] *= inv;
    }
    // zero padding region [257, 324)
    for (int idx = tid; idx < 8 * 68; idx += 256) {
        int qq = idx / 68; int jc = 257 + idx % 68;
        if (jc < 324) sP[qq][jc] = 0.f;
    }

    // ---- pass 2: O = P @ V (warp w owns dims [8w,8w+8)) ----
    float acc[8];
#pragma unroll
    for (int d = 0; d < 8; d++) acc[d] = 0.f;

    for (int j0 = 0; j0 < STOK; j0 += 64) {
        int rows = min(64, STOK - j0);
        __syncthreads();
        for (int lin = tid; lin < 1024; lin += 256) {
            int j = lin >> 4, d4 = (lin & 15) << 2;
            float4 v = make_float4(0.f, 0.f, 0.f, 0.f);
            if (j < rows)
                v = *(const float4*)&qkv[((size_t)(b*STOK + j0 + j))*QKVN + 2048 + h*HD_ + d4];
            *(float4*)&sKV[j][d4] = v;
        }
        __syncthreads();
#pragma unroll
        for (int jjg = 0; jjg < 16; jjg++) {
            int jj = jjg * 4 + jg;
            float p = sP[q][j0 + jj];
            float4 v0 = *(const float4*)&sKV[jj][w*8];
            float4 v1 = *(const float4*)&sKV[jj][w*8 + 4];
            acc[0] += p * v0.x; acc[1] += p * v0.y; acc[2] += p * v0.z; acc[3] += p * v0.w;
            acc[4] += p * v1.x; acc[5] += p * v1.y; acc[6] += p * v1.z; acc[7] += p * v1.w;
        }
    }
#pragma unroll
    for (int d = 0; d < 8; d++) {
        acc[d] += __shfl_xor_sync(0xffffffffu, acc[d], 1);
        acc[d] += __shfl_xor_sync(0xffffffffu, acc[d], 2);
    }
    if (i0 + q < STOK) {
        size_t base = ((size_t)(b*STOK + i0 + q))*DD + h*HD_ + w*8;
        int d0 = jg * 2;
#pragma unroll
        for (int e = 0; e < 2; e++) {
            __nv_bfloat16 hh, ll; split_w(acc[d0 + e], hh, ll);
            oH[base + d0 + e] = hh;
            oL[base + d0 + e] = ll;
        }
    }
}

// ---------------- PGSA gating + residual ----------------
__global__ void pgsa_kernel(const float* __restrict__ XF, const float* __restrict__ RES,
                            __nv_bfloat16* __restrict__ tokH, __nv_bfloat16* __restrict__ tokL)
{
    __shared__ float red[256];
    int d = blockIdx.x % DD;
    int b = blockIdx.x / DD;
    int n = threadIdx.x;

    float t = XF[((size_t)(b * STOK) + 1 + n) * DD + d];

    red[n] = t; __syncthreads();
    for (int off = 128; off; off >>= 1) { if (n < off) red[n] += red[n + off]; __syncthreads(); }
    float mu = red[0] * (1.f / NTOK);
    __syncthreads();

    float dm = t - mu;
    float xm2 = dm * dm;
    red[n] = xm2; __syncthreads();
    for (int off = 128; off; off >>= 1) { if (n < off) red[n] += red[n + off]; __syncthreads(); }
    float s2 = red[0];

    float y = xm2 / (4.f * (s2 * (1.f / 255.f) + 1e-4f)) + 0.5f;
    float sig = 1.f / (1.f + __expf(-y));
    float v = t * sig + RES[((size_t)(b * NTOK + n)) * DD + d];
    __nv_bfloat16 hh, ll; split_w(v, hh, ll);
    size_t o = ((size_t)(b * NTOK + n)) * DD + d;
    tokH[o] = hh; tokL[o] = ll;
}

// ---------------- unpatchify ----------------
__global__ void unpatch_kernel(const float* __restrict__ pred, float* __restrict__ out)
{
    int idx = blockIdx.x * blockDim.x + threadIdx.x;
    const int total = BB * 2 * IMG * IMG;
    if (idx >= total) return;
    int r  = idx % (2 * IMG * IMG);
    int b  = idx / (2 * IMG * IMG);
    int c  = r / (IMG * IMG);
    int r2 = r % (IMG * IMG);
    int y  = r2 / IMG, x = r2 % IMG;
    int h = y >> 4, p = y & 15, w = x >> 4, q = x & 15;
    out[idx] = pred[((size_t)(b * NTOK + h * HPP + w)) * (PP * PP * 2) + ((p * 16 + q) * 2 + c)];
}

// ---------------- host orchestration ----------------
#define GEMM_SMEM (8 * 128 * 40 * 2)

static inline void launch_gemm(int epi,
                               const __nv_bfloat16* Ah, const __nv_bfloat16* Al,
                               const __nv_bfloat16* Bh, const __nv_bfloat16* Bl,
                               const float* bias, float* Cf,
                               __nv_bfloat16* Ch, __nv_bfloat16* Cl,
                               const float* R, int M, int Nn, int K)
{
    dim3 grid(Nn / 128, (M + 127) / 128);
    if (epi == 0)      tgemm<0><<<grid, 256, GEMM_SMEM>>>(Ah, Al, Bh, Bl, bias, Cf, Ch, Cl, R, M, Nn, K);
    else if (epi == 1) tgemm<1><<<grid, 256, GEMM_SMEM>>>(Ah, Al, Bh, Bl, bias, Cf, Ch, Cl, R, M, Nn, K);
    else               tgemm<2><<<grid, 256, GEMM_SMEM>>>(Ah, Al, Bh, Bl, bias, Cf, Ch, Cl, R, M, Nn, K);
}

extern "C" void kernel_launch(void* const* d_in, const int* in_sizes, int n_in,
                              void* d_out, int out_size)
{
    const float* imgs     = (const float*)d_in[0];
    const float* patch_w  = (const float*)d_in[1];
    const float* patch_b  = (const float*)d_in[2];
    const float* cls_tok  = (const float*)d_in[3];
    const float* ln1_w    = (const float*)d_in[4];
    const float* ln1_b    = (const float*)d_in[5];
    const float* wq       = (const float*)d_in[6];
    const float* wk       = (const float*)d_in[7];
    const float* wv       = (const float*)d_in[8];
    const float* bq       = (const float*)d_in[9];
    const float* bk       = (const float*)d_in[10];
    const float* bv       = (const float*)d_in[11];
    const float* wo       = (const float*)d_in[12];
    const float* bo       = (const float*)d_in[13];
    const float* ln2_w    = (const float*)d_in[14];
    const float* ln2_b    = (const float*)d_in[15];
    const float* w1       = (const float*)d_in[16];
    const float* b1       = (const float*)d_in[17];
    const float* w2       = (const float*)d_in[18];
    const float* b2       = (const float*)d_in[19];
    const float* normf_w  = (const float*)d_in[20];
    const float* normf_b  = (const float*)d_in[21];
    const float* enpred_w = (const float*)d_in[22];
    const float* enpred_b = (const float*)d_in[23];

    cudaFuncSetAttribute(tgemm<0>, cudaFuncAttributeMaxDynamicSharedMemorySize, GEMM_SMEM);
    cudaFuncSetAttribute(tgemm<1>, cudaFuncAttributeMaxDynamicSharedMemorySize, GEMM_SMEM);
    cudaFuncSetAttribute(tgemm<2>, cudaFuncAttributeMaxDynamicSharedMemorySize, GEMM_SMEM);

    float *x, *h, *qkv, *res, *pred, *bqkv;
    cudaGetSymbolAddress((void**)&x,    g_x);
    cudaGetSymbolAddress((void**)&h,    g_h);
    cudaGetSymbolAddress((void**)&qkv,  g_qkv);
    cudaGetSymbolAddress((void**)&res,  g_res);
    cudaGetSymbolAddress((void**)&pred, g_pred);
    cudaGetSymbolAddress((void**)&bqkv, g_bqkv);

    __nv_bfloat16 *hH,*hL,*oH,*oL,*mlpH,*mlpL,*pH,*pL,*tokH,*tokL;
    cudaGetSymbolAddress((void**)&hH,   g_hH);   cudaGetSymbolAddress((void**)&hL,   g_hL);
    cudaGetSymbolAddress((void**)&oH,   g_oH);   cudaGetSymbolAddress((void**)&oL,   g_oL);
    cudaGetSymbolAddress((void**)&mlpH, g_mlpH); cudaGetSymbolAddress((void**)&mlpL, g_mlpL);
    cudaGetSymbolAddress((void**)&pH,   g_pH);   cudaGetSymbolAddress((void**)&pL,   g_pL);
    cudaGetSymbolAddress((void**)&tokH, g_tokH); cudaGetSymbolAddress((void**)&tokL, g_tokL);

    __nv_bfloat16 *WqkvH,*WqkvL,*WoH,*WoL,*W1H,*W1L,*W2H,*W2L,*WpH,*WpL,*WprH,*WprL;
    cudaGetSymbolAddress((void**)&WqkvH, g_WqkvH); cudaGetSymbolAddress((void**)&WqkvL, g_WqkvL);
    cudaGetSymbolAddress((void**)&WoH,   g_WoH);   cudaGetSymbolAddress((void**)&WoL,   g_WoL);
    cudaGetSymbolAddress((void**)&W1H,   g_W1H);   cudaGetSymbolAddress((void**)&W1L,   g_W1L);
    cudaGetSymbolAddress((void**)&W2H,   g_W2H);   cudaGetSymbolAddress((void**)&W2L,   g_W2L);
    cudaGetSymbolAddress((void**)&WpH,   g_WpH);   cudaGetSymbolAddress((void**)&WpL,   g_WpL);
    cudaGetSymbolAddress((void**)&WprH,  g_WprH);  cudaGetSymbolAddress((void**)&WprL,  g_WprL);

    const int Mtok = BB * STOK;   // 2056
    const int Mpat = BB * NTOK;   // 2048
    dim3 tb(32, 8);

    // ---- weight preprocessing (transpose + split) ----
    tsplit_kernel<<<dim3(32, 32, LL), tb>>>(wq, (size_t)DD * DD, WqkvH, WqkvL, (size_t)QKVN * DD, 0,    DD, DD);
    tsplit_kernel<<<dim3(32, 32, LL), tb>>>(wk, (size_t)DD * DD, WqkvH, WqkvL, (size_t)QKVN * DD, 1024, DD, DD);
    tsplit_kernel<<<dim3(32, 32, LL), tb>>>(wv, (size_t)DD * DD, WqkvH, WqkvL, (size_t)QKVN * DD, 2048, DD, DD);
    tsplit_kernel<<<dim3(32, 32, LL), tb>>>(wo, (size_t)DD * DD, WoH, WoL, (size_t)DD * DD, 0, DD, DD);
    tsplit_kernel<<<dim3(128, 32, LL), tb>>>(w1, (size_t)DD * DFF_, W1H, W1L, (size_t)DFF_ * DD, 0, DD, DFF_);
    tsplit_kernel<<<dim3(32, 128, LL), tb>>>(w2, (size_t)DFF_ * DD, W2H, W2L, (size_t)DD * DFF_, 0, DFF_, DD);
    tsplit_kernel<<<dim3(32, 16, 1), tb>>>(patch_w, 0, WpH, WpL, 0, 0, KPAT, DD);
    tsplit_kernel<<<dim3(16, 32, 1), tb>>>(enpred_w, 0, WprH, WprL, 0, 0, DD, 512);
    concat_bias_kernel<<<(LL * QKVN + 255) / 256, 256>>>(bq, bk, bv, bqkv);

    // ---- patch embed ----
    im2col_kernel<<<(Mpat * KPAT + 255) / 256, 256>>>(imgs, pH, pL);
    launch_gemm(0, pH, pL, WpH, WpL, patch_b, res, nullptr, nullptr, nullptr, Mpat, DD, KPAT);
    build_x_kernel<<<(BB * STOK * DD + 255) / 256, 256>>>(res, cls_tok, x);

    for (int i = 0; i < LL; i++) {
        const size_t bOff = (size_t)i * DD;
        ln_kernel<<<Mtok, 256>>>(x, ln1_w + bOff, ln1_b + bOff, nullptr, hH, hL);
        launch_gemm(0, hH, hL, WqkvH + (size_t)i * QKVN * DD, WqkvL + (size_t)i * QKVN * DD,
                    bqkv + (size_t)i * QKVN, qkv, nullptr, nullptr, nullptr, Mtok, QKVN, DD);
        attn_kernel<<<dim3((STOK + 7) / 8, NHH, BB), 256>>>(qkv, oH, oL);
        launch_gemm(1, oH, oL, WoH + (size_t)i * DD * DD, WoL + (size_t)i * DD * DD,
                    bo + bOff, x, nullptr, nullptr, x, Mtok, DD, DD);
        ln_kernel<<<Mtok, 256>>>(x, ln2_w + bOff, ln2_b + bOff, nullptr, hH, hL);
        launch_gemm(2, hH, hL, W1H + (size_t)i * DFF_ * DD, W1L + (size_t)i * DFF_ * DD,
                    b1 + (size_t)i * DFF_, nullptr, mlpH, mlpL, nullptr, Mtok, DFF_, DD);
        launch_gemm(1, mlpH, mlpL, W2H + (size_t)i * DD * DFF_, W2L + (size_t)i * DD * DFF_,
                    b2 + bOff, x, nullptr, nullptr, x, Mtok, DD, DFF_);
    }

    // ---- tail ----
    ln_kernel<<<Mtok, 256>>>(x, normf_w, normf_b, h, nullptr, nullptr);
    pgsa_kernel<<<BB * DD, 256>>>(h, res, tokH, tokL);
    launch_gemm(0, tokH, tokL, WprH, WprL, enpred_b, pred, nullptr, nullptr, nullptr, Mpat, 512, DD);
    unpatch_kernel<<<(out_size + 255) / 256, 256>>>(pred, (float*)d_out);
}